// round 1
// baseline (speedup 1.0000x reference)
#include <cuda_runtime.h>
#include <math.h>

#define Ndim  64
#define Sdim  512
#define Hdim  1024
#define IOdim 64

// ---------------- scratch (no allocations allowed) ----------------
__device__ float g_P  [(size_t)Ndim * IOdim * Sdim];     // softmax probs [n][i][s]   8 MB
__device__ float g_mix[(size_t)Ndim * IOdim * Hdim];     // mix           [n][i][h]  16 MB
__device__ float g_T  [(size_t)Ndim * IOdim * Hdim];     // tanh(o)       [n][i][h]  16 MB
__device__ float g_c0p[(size_t)4 * IOdim * Hdim];        // c0 partials [ks][i][h]    1 MB
__device__ float g_part[(size_t)128 * Ndim * IOdim];     // logits partials [ch][n][j] 2 MB

// 4x4 outer-product micro-tile
#define MICRO_FMA(c, a, b)                                                  \
    c[0][0]+=a.x*b.x; c[0][1]+=a.x*b.y; c[0][2]+=a.x*b.z; c[0][3]+=a.x*b.w; \
    c[1][0]+=a.y*b.x; c[1][1]+=a.y*b.y; c[1][2]+=a.y*b.z; c[1][3]+=a.y*b.w; \
    c[2][0]+=a.z*b.x; c[2][1]+=a.z*b.y; c[2][2]+=a.z*b.z; c[2][3]+=a.z*b.w; \
    c[3][0]+=a.w*b.x; c[3][1]+=a.w*b.y; c[3][2]+=a.w*b.z; c[3][3]+=a.w*b.w;

// Generic 64x64 output tile GEMM: C[64,64] = A[64,Ktot] (row-major, lda) *
// B[Ktot,64] (row-major, ldb). 256 threads, each owns a 4x4 micro-tile.
// Shared tiles are K=16 deep; As stored transposed [k][i] so both operand
// reads are LDS.128. Stride 68 floats keeps 16B alignment + few conflicts.
__device__ __forceinline__ void gemm_tile_64x64(
    const float* __restrict__ A, size_t lda,
    const float* __restrict__ B, size_t ldb,
    int Ktot, float c[4][4],
    float (&As)[16][68], float (&Bs)[16][68])
{
    const int tid  = threadIdx.x;
    const int la_i = tid >> 2;          // 0..63  (A row)
    const int la_k = (tid & 3) * 4;     // 0..12  (A k-offset, float4)
    const int lb_k = tid >> 4;          // 0..15  (B row within tile)
    const int lb_h = (tid & 15) * 4;    // 0..60  (B col, float4)
    const int ir   = tid >> 4;          // micro-tile row group
    const int hq   = tid & 15;          // micro-tile col group

    for (int k0 = 0; k0 < Ktot; k0 += 16) {
        float4 va = *reinterpret_cast<const float4*>(A + (size_t)la_i * lda + k0 + la_k);
        float4 vb = *reinterpret_cast<const float4*>(B + (size_t)(k0 + lb_k) * ldb + lb_h);
        As[la_k + 0][la_i] = va.x;
        As[la_k + 1][la_i] = va.y;
        As[la_k + 2][la_i] = va.z;
        As[la_k + 3][la_i] = va.w;
        *reinterpret_cast<float4*>(&Bs[lb_k][lb_h]) = vb;
        __syncthreads();
#pragma unroll
        for (int k = 0; k < 16; k++) {
            float4 a = *reinterpret_cast<float4*>(&As[k][ir * 4]);
            float4 b = *reinterpret_cast<float4*>(&Bs[k][hq * 4]);
            MICRO_FMA(c, a, b)
        }
        __syncthreads();
    }
}

// ---------------------------------------------------------------------------
// K_c0: c0 partials = OS @ Wo[H:2H, :] (+ bo on slice 0).  grid (16 htile, 4 ksplit)
// ---------------------------------------------------------------------------
__global__ __launch_bounds__(256)
void k_c0(const float* __restrict__ OS, const float* __restrict__ Wo,
          const float* __restrict__ bo)
{
    __shared__ float As[16][68];
    __shared__ float Bs[16][68];
    const int ks    = blockIdx.y;
    const int hbase = blockIdx.x * 64;
    float c[4][4] = {};

    const float* Ap = OS + ks * 256;                                   // rows i, k-slab
    const float* Bp = Wo + (size_t)(Hdim + ks * 256) * Hdim + hbase;   // bottom half of Wo
    gemm_tile_64x64(Ap, Hdim, Bp, Hdim, 256, c, As, Bs);

    const int tid = threadIdx.x;
    const int ir = tid >> 4, hq = tid & 15;
#pragma unroll
    for (int ii = 0; ii < 4; ii++) {
        const int i = ir * 4 + ii;
        const int h = hbase + hq * 4;
        float4 v = make_float4(c[ii][0], c[ii][1], c[ii][2], c[ii][3]);
        if (ks == 0) {
            const float4 b = *reinterpret_cast<const float4*>(bo + h);
            v.x += b.x; v.y += b.y; v.z += b.z; v.w += b.w;
        }
        *reinterpret_cast<float4*>(g_c0p + ((size_t)ks * IOdim + i) * Hdim + h) = v;
    }
}

// ---------------------------------------------------------------------------
// K1: fused attention scores + softmax.  grid (4 itile, 64 n), block 256.
// Block computes A[16 i][512 s] for one n (K = 1024 over h), then softmax
// over the full s-row in registers/shuffles, writes P.
// ---------------------------------------------------------------------------
__global__ __launch_bounds__(256, 2)
void k_scores_softmax(const float* __restrict__ states, const float* __restrict__ OS)
{
    __shared__ float Ss[512][20];    // states tile [s][k], k-contiguous (pad 20)
    __shared__ float Os[16][20];     // output_set tile [i][k]
    __shared__ float wred[4][2][4];  // cross-warp reduce [ti][warp-half][ii]

    const int n   = blockIdx.y;
    const int i0  = blockIdx.x * 16;
    const int tid = threadIdx.x;
    const int ti  = tid >> 6;        // 0..3  (i group: 4 rows each)
    const int ts  = tid & 63;        // 0..63 (s group: 8 cols, stride 64)

    const float* stn = states + (size_t)n * Sdim * Hdim;

    float c[4][8];
#pragma unroll
    for (int ii = 0; ii < 4; ii++)
#pragma unroll
        for (int si = 0; si < 8; si++) c[ii][si] = 0.f;

    for (int k0 = 0; k0 < Hdim; k0 += 16) {
        // stage states tile: 512 x 16 floats
#pragma unroll
        for (int r = 0; r < 8; r++) {
            const int f  = tid + 256 * r;
            const int kq = f & 3, s = f >> 2;
            float4 v = *reinterpret_cast<const float4*>(stn + (size_t)s * Hdim + k0 + kq * 4);
            *reinterpret_cast<float4*>(&Ss[s][kq * 4]) = v;
        }
        if (tid < 64) {
            const int kq = tid & 3, i = tid >> 2;
            float4 v = *reinterpret_cast<const float4*>(OS + (size_t)(i0 + i) * Hdim + k0 + kq * 4);
            *reinterpret_cast<float4*>(&Os[i][kq * 4]) = v;
        }
        __syncthreads();
#pragma unroll
        for (int kk = 0; kk < 16; kk += 4) {
            float4 a[4], b[8];
#pragma unroll
            for (int ii = 0; ii < 4; ii++) a[ii] = *reinterpret_cast<float4*>(&Os[ti * 4 + ii][kk]);
#pragma unroll
            for (int si = 0; si < 8; si++) b[si] = *reinterpret_cast<float4*>(&Ss[ts + 64 * si][kk]);
#pragma unroll
            for (int ii = 0; ii < 4; ii++)
#pragma unroll
                for (int si = 0; si < 8; si++) {
                    c[ii][si] += a[ii].x * b[si].x;
                    c[ii][si] += a[ii].y * b[si].y;
                    c[ii][si] += a[ii].z * b[si].z;
                    c[ii][si] += a[ii].w * b[si].w;
                }
        }
        __syncthreads();
    }

    // ---- softmax over s (512) per row i ----
    const int wh = ts >> 5;  // which warp-half of this ti group
    float mx[4];
#pragma unroll
    for (int ii = 0; ii < 4; ii++) {
        float v = c[ii][0];
#pragma unroll
        for (int si = 1; si < 8; si++) v = fmaxf(v, c[ii][si]);
#pragma unroll
        for (int off = 16; off > 0; off >>= 1) v = fmaxf(v, __shfl_xor_sync(0xffffffffu, v, off));
        mx[ii] = v;
    }
    if ((ts & 31) == 0) {
#pragma unroll
        for (int ii = 0; ii < 4; ii++) wred[ti][wh][ii] = mx[ii];
    }
    __syncthreads();
#pragma unroll
    for (int ii = 0; ii < 4; ii++) mx[ii] = fmaxf(wred[ti][0][ii], wred[ti][1][ii]);
    __syncthreads();

    float sm[4];
#pragma unroll
    for (int ii = 0; ii < 4; ii++) {
        float s = 0.f;
#pragma unroll
        for (int si = 0; si < 8; si++) {
            const float e = __expf(c[ii][si] - mx[ii]);
            c[ii][si] = e;
            s += e;
        }
#pragma unroll
        for (int off = 16; off > 0; off >>= 1) s += __shfl_xor_sync(0xffffffffu, s, off);
        sm[ii] = s;
    }
    if ((ts & 31) == 0) {
#pragma unroll
        for (int ii = 0; ii < 4; ii++) wred[ti][wh][ii] = sm[ii];
    }
    __syncthreads();

    float* Pn = g_P + (size_t)n * IOdim * Sdim;
#pragma unroll
    for (int ii = 0; ii < 4; ii++) {
        const float inv = 1.0f / (wred[ti][0][ii] + wred[ti][1][ii]);
        const int i = i0 + ti * 4 + ii;
#pragma unroll
        for (int si = 0; si < 8; si++)
            Pn[(size_t)i * Sdim + ts + 64 * si] = c[ii][si] * inv;
    }
}

// ---------------------------------------------------------------------------
// K3: mix[n] = P[n] @ states[n].  grid (16 htile, 64 n)
// ---------------------------------------------------------------------------
__global__ __launch_bounds__(256)
void k_mix(const float* __restrict__ states)
{
    __shared__ float As[16][68];
    __shared__ float Bs[16][68];
    const int n     = blockIdx.y;
    const int hbase = blockIdx.x * 64;
    float c[4][4] = {};

    const float* Pn  = g_P + (size_t)n * IOdim * Sdim;
    const float* stn = states + (size_t)n * Sdim * Hdim + hbase;
    gemm_tile_64x64(Pn, Sdim, stn, Hdim, Sdim, c, As, Bs);

    const int tid = threadIdx.x;
    const int ir = tid >> 4, hq = tid & 15;
    float* mixn = g_mix + (size_t)n * IOdim * Hdim;
#pragma unroll
    for (int ii = 0; ii < 4; ii++) {
        float4 v = make_float4(c[ii][0], c[ii][1], c[ii][2], c[ii][3]);
        *reinterpret_cast<float4*>(mixn + (size_t)(ir * 4 + ii) * Hdim + hbase + hq * 4) = v;
    }
}

// ---------------------------------------------------------------------------
// K4: t = tanh(mix[n] @ Wo[:H, :] + c0).  grid (16 htile, 64 n)
// ---------------------------------------------------------------------------
__global__ __launch_bounds__(256)
void k_outlin(const float* __restrict__ Wo)
{
    __shared__ float As[16][68];
    __shared__ float Bs[16][68];
    const int n     = blockIdx.y;
    const int hbase = blockIdx.x * 64;
    float c[4][4] = {};

    const float* mixn = g_mix + (size_t)n * IOdim * Hdim;
    gemm_tile_64x64(mixn, Hdim, Wo + hbase, Hdim, Hdim, c, As, Bs);

    const int tid = threadIdx.x;
    const int ir = tid >> 4, hq = tid & 15;
    float* Tn = g_T + (size_t)n * IOdim * Hdim;
#pragma unroll
    for (int ii = 0; ii < 4; ii++) {
        const int i = ir * 4 + ii;
        const int h = hbase + hq * 4;
        float4 c0 = make_float4(0.f, 0.f, 0.f, 0.f);
#pragma unroll
        for (int ks = 0; ks < 4; ks++) {
            const float4 p = *reinterpret_cast<const float4*>(
                g_c0p + ((size_t)ks * IOdim + i) * Hdim + h);
            c0.x += p.x; c0.y += p.y; c0.z += p.z; c0.w += p.w;
        }
        float4 v;
        v.x = tanhf(c[ii][0] + c0.x);
        v.y = tanhf(c[ii][1] + c0.y);
        v.z = tanhf(c[ii][2] + c0.z);
        v.w = tanhf(c[ii][3] + c0.w);
        *reinterpret_cast<float4*>(Tn + (size_t)i * Hdim + h) = v;
    }
}

// ---------------------------------------------------------------------------
// K5: logits partials.  [64 n] x [64 j], K = 65536, split into 128 chunks.
// ---------------------------------------------------------------------------
__global__ __launch_bounds__(256)
void k_logits(const float* __restrict__ Wc)
{
    __shared__ float As[16][68];
    __shared__ float Bs[16][68];
    const int chunk = blockIdx.x;     // 0..127
    const int kb    = chunk * 512;
    float c[4][4] = {};

    gemm_tile_64x64(g_T + kb, (size_t)IOdim * Hdim,
                    Wc + (size_t)kb * IOdim, IOdim, 512, c, As, Bs);

    const int tid = threadIdx.x;
    const int nr = tid >> 4, jq = tid & 15;
#pragma unroll
    for (int ii = 0; ii < 4; ii++) {
        float4 v = make_float4(c[ii][0], c[ii][1], c[ii][2], c[ii][3]);
        *reinterpret_cast<float4*>(
            g_part + ((size_t)chunk * Ndim + nr * 4 + ii) * IOdim + jq * 4) = v;
    }
}

// ---------------------------------------------------------------------------
// K6: reduce partials + bc -> out[n][j]
// ---------------------------------------------------------------------------
__global__ __launch_bounds__(256)
void k_reduce(const float* __restrict__ bc, float* __restrict__ out)
{
    const int gid = blockIdx.x * 256 + threadIdx.x;   // 0..4095
    const int j   = gid & 63;
    float acc = bc[j];
#pragma unroll 8
    for (int ch = 0; ch < 128; ch++) acc += g_part[(size_t)ch * 4096 + gid];
    out[gid] = acc;
}

// ---------------------------------------------------------------------------
extern "C" void kernel_launch(void* const* d_in, const int* in_sizes, int n_in,
                              void* d_out, int out_size)
{
    const float* states = (const float*)d_in[0];  // [64, 512, 1024]
    const float* OS     = (const float*)d_in[1];  // [64, 1024]
    const float* Wo     = (const float*)d_in[2];  // [2048, 1024]
    const float* bo     = (const float*)d_in[3];  // [1024]
    const float* Wc     = (const float*)d_in[4];  // [65536, 64]
    const float* bc     = (const float*)d_in[5];  // [64]
    float* out = (float*)d_out;                   // [64, 64]

    k_c0<<<dim3(16, 4), 256>>>(OS, Wo, bo);
    k_scores_softmax<<<dim3(4, 64), 256>>>(states, OS);
    k_mix<<<dim3(16, 64), 256>>>(states);
    k_outlin<<<dim3(16, 64), 256>>>(Wo);
    k_logits<<<128, 256>>>(Wc);
    k_reduce<<<16, 256>>>(bc, out);
}

// round 2
// speedup vs baseline: 1.4354x; 1.4354x over previous
#include <cuda_runtime.h>
#include <math.h>

#define Ndim  64
#define Sdim  512
#define Hdim  1024
#define IOdim 64

// ---------------- scratch (no allocations allowed) ----------------
__device__ float g_S  [(size_t)Ndim * IOdim * Sdim];     // raw scores  [n][i][s]   8 MB
__device__ float g_P  [(size_t)Ndim * IOdim * Sdim];     // softmax     [n][i][s]   8 MB
__device__ float g_mix[(size_t)Ndim * IOdim * Hdim];     // mix         [n][i][h]  16 MB
__device__ float g_T  [(size_t)Ndim * IOdim * Hdim];     // tanh(o)     [n][i][h]  16 MB
__device__ float g_c0p[(size_t)8 * IOdim * Hdim];        // c0 partials [ks][i][h]  2 MB
__device__ float g_c0 [(size_t)IOdim * Hdim];            // c0 final    [i][h]    0.25 MB
__device__ float g_part[(size_t)128 * Ndim * IOdim];     // logits partials         2 MB

// ===========================================================================
// tf32 mma.sync machinery
// ===========================================================================
__device__ __forceinline__ unsigned f2tf(float x) {
    unsigned u; asm("cvt.rna.tf32.f32 %0, %1;" : "=r"(u) : "f"(x)); return u;
}
__device__ __forceinline__ void mma8(float (&d)[4], const unsigned (&a)[4],
                                     const unsigned (&b)[2]) {
    asm volatile(
        "mma.sync.aligned.m16n8k8.row.col.f32.tf32.tf32.f32 "
        "{%0,%1,%2,%3}, {%4,%5,%6,%7}, {%8,%9}, {%0,%1,%2,%3};"
        : "+f"(d[0]), "+f"(d[1]), "+f"(d[2]), "+f"(d[3])
        : "r"(a[0]), "r"(a[1]), "r"(a[2]), "r"(a[3]), "r"(b[0]), "r"(b[1]));
}

constexpr int ALD    = 20;    // As [64][k16] row stride (bank-conflict free)
constexpr int BLD_NK = 20;    // Bs [n256][k16] row stride
constexpr int BLD_KN = 264;   // Bs [k16][n256] row stride (mod 32 == 8)

// C[64, 256] += A[64, K] (row-major, lda) * B  (either B[n][k] row-major when
// BKN=false, i.e. genuinely col-major k x n; or B[k][n] row-major when BKN=true).
// 8 warps, each owns warp tile m64 x n32. CORRECT enables 3-term tf32 split
// (error ~2^-22 instead of ~2^-11).
template<bool BKN, bool CORRECT>
__device__ __forceinline__ void gemm_mma(
    const float* __restrict__ A, int lda,
    const float* __restrict__ B, int ldb, int n0, int K,
    float* As, float* Bs, float (&acc)[4][4][4])
{
    const int tid  = threadIdx.x;
    const int lane = tid & 31, warp = tid >> 5;
    const int g = lane >> 2, t = lane & 3;
    const int nw = warp * 32;

    for (int k0 = 0; k0 < K; k0 += 16) {
        __syncthreads();
        {   // stage A tile [64][16]
            const int row = tid >> 2, kc = (tid & 3) * 4;
            float4 v = *reinterpret_cast<const float4*>(A + (size_t)row * lda + k0 + kc);
            *reinterpret_cast<float4*>(As + row * ALD + kc) = v;
        }
        if (BKN) {  // stage B tile [16][256]
            const int kr = tid >> 4, nc0 = (tid & 15) * 4;
            const float* Brow = B + (size_t)(k0 + kr) * ldb + n0;
#pragma unroll
            for (int j = 0; j < 4; j++) {
                float4 v = *reinterpret_cast<const float4*>(Brow + nc0 + 64 * j);
                *reinterpret_cast<float4*>(Bs + kr * BLD_KN + nc0 + 64 * j) = v;
            }
        } else {    // stage B tile [256][16]
            const int r0 = tid >> 2, kc = (tid & 3) * 4;
#pragma unroll
            for (int j = 0; j < 4; j++) {
                const int row = r0 + 64 * j;
                float4 v = *reinterpret_cast<const float4*>(
                    B + (size_t)(n0 + row) * ldb + k0 + kc);
                *reinterpret_cast<float4*>(Bs + row * BLD_NK + kc) = v;
            }
        }
        __syncthreads();

#pragma unroll
        for (int kk = 0; kk < 16; kk += 8) {
            unsigned Ah[4][4], Al[4][4];
#pragma unroll
            for (int mi = 0; mi < 4; mi++) {
                const int r = 16 * mi + g;
                float a0 = As[(r    ) * ALD + kk + t];
                float a1 = As[(r + 8) * ALD + kk + t];
                float a2 = As[(r    ) * ALD + kk + t + 4];
                float a3 = As[(r + 8) * ALD + kk + t + 4];
                Ah[mi][0] = f2tf(a0); Ah[mi][1] = f2tf(a1);
                Ah[mi][2] = f2tf(a2); Ah[mi][3] = f2tf(a3);
                if (CORRECT) {
                    Al[mi][0] = f2tf(a0 - __uint_as_float(Ah[mi][0]));
                    Al[mi][1] = f2tf(a1 - __uint_as_float(Ah[mi][1]));
                    Al[mi][2] = f2tf(a2 - __uint_as_float(Ah[mi][2]));
                    Al[mi][3] = f2tf(a3 - __uint_as_float(Ah[mi][3]));
                }
            }
#pragma unroll
            for (int ni = 0; ni < 4; ni++) {
                const int nbase = nw + ni * 8 + g;
                float b0, b1;
                if (BKN) {
                    b0 = Bs[(kk + t    ) * BLD_KN + nbase];
                    b1 = Bs[(kk + t + 4) * BLD_KN + nbase];
                } else {
                    b0 = Bs[nbase * BLD_NK + kk + t];
                    b1 = Bs[nbase * BLD_NK + kk + t + 4];
                }
                unsigned bh[2] = { f2tf(b0), f2tf(b1) };
                if (CORRECT) {
                    unsigned bl[2] = { f2tf(b0 - __uint_as_float(bh[0])),
                                       f2tf(b1 - __uint_as_float(bh[1])) };
#pragma unroll
                    for (int mi = 0; mi < 4; mi++) {
                        mma8(acc[mi][ni], Ah[mi], bh);
                        mma8(acc[mi][ni], Ah[mi], bl);
                        mma8(acc[mi][ni], Al[mi], bh);
                    }
                } else {
#pragma unroll
                    for (int mi = 0; mi < 4; mi++) mma8(acc[mi][ni], Ah[mi], bh);
                }
            }
        }
    }
}

// ===========================================================================
// K_c0 (mma, K-split): c0 partials = OS @ Wo[H + ks*128 .. ][:]  grid (4, 8)
// ===========================================================================
__global__ __launch_bounds__(256, 2)
void k_c0mma(const float* __restrict__ OS, const float* __restrict__ Wo)
{
    __shared__ float As[64 * ALD];
    __shared__ float Bs[16 * BLD_KN];
    const int ks = blockIdx.y;
    const int n0 = blockIdx.x * 256;
    float acc[4][4][4] = {};
    gemm_mma<true, true>(OS + ks * 128, Hdim,
                         Wo + (size_t)(Hdim + ks * 128) * Hdim, Hdim,
                         n0, 128, As, Bs, acc);
    const int lane = threadIdx.x & 31, warp = threadIdx.x >> 5;
    const int g = lane >> 2, t = lane & 3, nw = warp * 32;
    float* Cp = g_c0p + (size_t)ks * IOdim * Hdim;
#pragma unroll
    for (int mi = 0; mi < 4; mi++)
#pragma unroll
        for (int ni = 0; ni < 4; ni++) {
            const int r0 = 16 * mi + g, c = n0 + nw + ni * 8 + 2 * t;
            *reinterpret_cast<float2*>(Cp + (size_t)r0 * Hdim + c) =
                make_float2(acc[mi][ni][0], acc[mi][ni][1]);
            *reinterpret_cast<float2*>(Cp + (size_t)(r0 + 8) * Hdim + c) =
                make_float2(acc[mi][ni][2], acc[mi][ni][3]);
        }
}

__global__ __launch_bounds__(256)
void k_c0red(const float* __restrict__ bo)
{
    const int gid = blockIdx.x * 256 + threadIdx.x;   // 0..65535
    float acc = bo[gid & (Hdim - 1)];
#pragma unroll
    for (int p = 0; p < 8; p++) acc += g_c0p[(size_t)p * IOdim * Hdim + gid];
    g_c0[gid] = acc;
}

// ===========================================================================
// K_scores (mma, single-pass tf32 — softmax damps the error): grid (2, 64)
// ===========================================================================
__global__ __launch_bounds__(256, 2)
void k_scores(const float* __restrict__ states, const float* __restrict__ OS)
{
    __shared__ float As[64 * ALD];
    __shared__ float Bs[256 * BLD_NK];
    const int n = blockIdx.y, n0 = blockIdx.x * 256;
    float acc[4][4][4] = {};
    gemm_mma<false, false>(OS, Hdim, states + (size_t)n * Sdim * Hdim, Hdim,
                           n0, Hdim, As, Bs, acc);
    const int lane = threadIdx.x & 31, warp = threadIdx.x >> 5;
    const int g = lane >> 2, t = lane & 3, nw = warp * 32;
    float* Cn = g_S + (size_t)n * IOdim * Sdim;
#pragma unroll
    for (int mi = 0; mi < 4; mi++)
#pragma unroll
        for (int ni = 0; ni < 4; ni++) {
            const int r0 = 16 * mi + g, c = n0 + nw + ni * 8 + 2 * t;
            *reinterpret_cast<float2*>(Cn + (size_t)r0 * Sdim + c) =
                make_float2(acc[mi][ni][0], acc[mi][ni][1]);
            *reinterpret_cast<float2*>(Cn + (size_t)(r0 + 8) * Sdim + c) =
                make_float2(acc[mi][ni][2], acc[mi][ni][3]);
        }
}

// ===========================================================================
// K_softmax: one warp per (n,i) row of 512.  grid 512, block 256.
// ===========================================================================
__global__ __launch_bounds__(256)
void k_softmax()
{
    const int warp = threadIdx.x >> 5, lane = threadIdx.x & 31;
    const size_t row = (size_t)blockIdx.x * 8 + warp;         // 0..4095
    const float* src = g_S + row * Sdim;
    float*       dst = g_P + row * Sdim;

    float v[16];
    float mx = -1e30f;
#pragma unroll
    for (int q = 0; q < 16; q++) {
        v[q] = src[lane + 32 * q];
        mx = fmaxf(mx, v[q]);
    }
#pragma unroll
    for (int off = 16; off > 0; off >>= 1)
        mx = fmaxf(mx, __shfl_xor_sync(0xffffffffu, mx, off));
    float sum = 0.f;
#pragma unroll
    for (int q = 0; q < 16; q++) {
        v[q] = __expf(v[q] - mx);
        sum += v[q];
    }
#pragma unroll
    for (int off = 16; off > 0; off >>= 1)
        sum += __shfl_xor_sync(0xffffffffu, sum, off);
    const float inv = 1.0f / sum;
#pragma unroll
    for (int q = 0; q < 16; q++) dst[lane + 32 * q] = v[q] * inv;
}

// ===========================================================================
// K_mix (mma, corrected): mix[n] = P[n] @ states[n].  grid (4, 64)
// ===========================================================================
__global__ __launch_bounds__(256, 2)
void k_mix(const float* __restrict__ states)
{
    __shared__ float As[64 * ALD];
    __shared__ float Bs[16 * BLD_KN];
    const int n = blockIdx.y, n0 = blockIdx.x * 256;
    float acc[4][4][4] = {};
    gemm_mma<true, true>(g_P + (size_t)n * IOdim * Sdim, Sdim,
                         states + (size_t)n * Sdim * Hdim, Hdim,
                         n0, Sdim, As, Bs, acc);
    const int lane = threadIdx.x & 31, warp = threadIdx.x >> 5;
    const int g = lane >> 2, t = lane & 3, nw = warp * 32;
    float* Cn = g_mix + (size_t)n * IOdim * Hdim;
#pragma unroll
    for (int mi = 0; mi < 4; mi++)
#pragma unroll
        for (int ni = 0; ni < 4; ni++) {
            const int r0 = 16 * mi + g, c = n0 + nw + ni * 8 + 2 * t;
            *reinterpret_cast<float2*>(Cn + (size_t)r0 * Hdim + c) =
                make_float2(acc[mi][ni][0], acc[mi][ni][1]);
            *reinterpret_cast<float2*>(Cn + (size_t)(r0 + 8) * Hdim + c) =
                make_float2(acc[mi][ni][2], acc[mi][ni][3]);
        }
}

// ===========================================================================
// K_outlin (mma, corrected): t = tanh(mix[n] @ Wo[:H,:] + c0).  grid (4, 64)
// ===========================================================================
__global__ __launch_bounds__(256, 2)
void k_outlin(const float* __restrict__ Wo)
{
    __shared__ float As[64 * ALD];
    __shared__ float Bs[16 * BLD_KN];
    const int n = blockIdx.y, n0 = blockIdx.x * 256;
    float acc[4][4][4] = {};
    gemm_mma<true, true>(g_mix + (size_t)n * IOdim * Hdim, Hdim,
                         Wo, Hdim, n0, Hdim, As, Bs, acc);
    const int lane = threadIdx.x & 31, warp = threadIdx.x >> 5;
    const int g = lane >> 2, t = lane & 3, nw = warp * 32;
    float* Tn = g_T + (size_t)n * IOdim * Hdim;
#pragma unroll
    for (int mi = 0; mi < 4; mi++)
#pragma unroll
        for (int ni = 0; ni < 4; ni++) {
            const int r0 = 16 * mi + g, c = n0 + nw + ni * 8 + 2 * t;
            float2 w0, w1;
            w0.x = tanhf(acc[mi][ni][0] + g_c0[(size_t)r0 * Hdim + c]);
            w0.y = tanhf(acc[mi][ni][1] + g_c0[(size_t)r0 * Hdim + c + 1]);
            w1.x = tanhf(acc[mi][ni][2] + g_c0[(size_t)(r0 + 8) * Hdim + c]);
            w1.y = tanhf(acc[mi][ni][3] + g_c0[(size_t)(r0 + 8) * Hdim + c + 1]);
            *reinterpret_cast<float2*>(Tn + (size_t)r0 * Hdim + c) = w0;
            *reinterpret_cast<float2*>(Tn + (size_t)(r0 + 8) * Hdim + c) = w1;
        }
}

// ===========================================================================
// K_logits (fp32 FFMA, keeps final reduction exact) + reduce — as round 1
// ===========================================================================
#define MICRO_FMA(c, a, b)                                                  \
    c[0][0]+=a.x*b.x; c[0][1]+=a.x*b.y; c[0][2]+=a.x*b.z; c[0][3]+=a.x*b.w; \
    c[1][0]+=a.y*b.x; c[1][1]+=a.y*b.y; c[1][2]+=a.y*b.z; c[1][3]+=a.y*b.w; \
    c[2][0]+=a.z*b.x; c[2][1]+=a.z*b.y; c[2][2]+=a.z*b.z; c[2][3]+=a.z*b.w; \
    c[3][0]+=a.w*b.x; c[3][1]+=a.w*b.y; c[3][2]+=a.w*b.z; c[3][3]+=a.w*b.w;

__device__ __forceinline__ void gemm_tile_64x64_f(
    const float* __restrict__ A, size_t lda,
    const float* __restrict__ B, size_t ldb,
    int Ktot, float c[4][4],
    float (&As)[16][68], float (&Bs)[16][68])
{
    const int tid  = threadIdx.x;
    const int la_i = tid >> 2;
    const int la_k = (tid & 3) * 4;
    const int lb_k = tid >> 4;
    const int lb_h = (tid & 15) * 4;
    const int ir   = tid >> 4;
    const int hq   = tid & 15;

    for (int k0 = 0; k0 < Ktot; k0 += 16) {
        float4 va = *reinterpret_cast<const float4*>(A + (size_t)la_i * lda + k0 + la_k);
        float4 vb = *reinterpret_cast<const float4*>(B + (size_t)(k0 + lb_k) * ldb + lb_h);
        As[la_k + 0][la_i] = va.x;
        As[la_k + 1][la_i] = va.y;
        As[la_k + 2][la_i] = va.z;
        As[la_k + 3][la_i] = va.w;
        *reinterpret_cast<float4*>(&Bs[lb_k][lb_h]) = vb;
        __syncthreads();
#pragma unroll
        for (int k = 0; k < 16; k++) {
            float4 a = *reinterpret_cast<float4*>(&As[k][ir * 4]);
            float4 b = *reinterpret_cast<float4*>(&Bs[k][hq * 4]);
            MICRO_FMA(c, a, b)
        }
        __syncthreads();
    }
}

__global__ __launch_bounds__(256)
void k_logits(const float* __restrict__ Wc)
{
    __shared__ float As[16][68];
    __shared__ float Bs[16][68];
    const int chunk = blockIdx.x;
    const int kb    = chunk * 512;
    float c[4][4] = {};
    gemm_tile_64x64_f(g_T + kb, (size_t)IOdim * Hdim,
                      Wc + (size_t)kb * IOdim, IOdim, 512, c, As, Bs);
    const int tid = threadIdx.x;
    const int nr = tid >> 4, jq = tid & 15;
#pragma unroll
    for (int ii = 0; ii < 4; ii++) {
        float4 v = make_float4(c[ii][0], c[ii][1], c[ii][2], c[ii][3]);
        *reinterpret_cast<float4*>(
            g_part + ((size_t)chunk * Ndim + nr * 4 + ii) * IOdim + jq * 4) = v;
    }
}

__global__ __launch_bounds__(256)
void k_reduce(const float* __restrict__ bc, float* __restrict__ out)
{
    const int gid = blockIdx.x * 256 + threadIdx.x;
    const int j   = gid & 63;
    float acc = bc[j];
#pragma unroll 8
    for (int ch = 0; ch < 128; ch++) acc += g_part[(size_t)ch * 4096 + gid];
    out[gid] = acc;
}

// ===========================================================================
extern "C" void kernel_launch(void* const* d_in, const int* in_sizes, int n_in,
                              void* d_out, int out_size)
{
    const float* states = (const float*)d_in[0];  // [64, 512, 1024]
    const float* OS     = (const float*)d_in[1];  // [64, 1024]
    const float* Wo     = (const float*)d_in[2];  // [2048, 1024]
    const float* bo     = (const float*)d_in[3];  // [1024]
    const float* Wc     = (const float*)d_in[4];  // [65536, 64]
    const float* bc     = (const float*)d_in[5];  // [64]
    float* out = (float*)d_out;                   // [64, 64]

    k_c0mma  <<<dim3(4, 8),  256>>>(OS, Wo);
    k_c0red  <<<256,         256>>>(bo);
    k_scores <<<dim3(2, 64), 256>>>(states, OS);
    k_softmax<<<512,         256>>>();
    k_mix    <<<dim3(4, 64), 256>>>(states);
    k_outlin <<<dim3(4, 64), 256>>>(Wo);
    k_logits <<<128,         256>>>(Wc);
    k_reduce <<<16,          256>>>(bc, out);
}

// round 3
// speedup vs baseline: 1.7003x; 1.1845x over previous
#include <cuda_runtime.h>
#include <math.h>

#define Ndim  64
#define Sdim  512
#define Hdim  1024
#define IOdim 64

// ---------------- scratch (no allocations allowed) ----------------
// "hp/lp" arrays are bf16x2 words: word w of a row packs k=2w (lo 16) and
// k=2w+1 (hi 16); value = float(hp) + float(lp) reproduces fp32 to ~2^-18.
__device__ unsigned g_OShp[(size_t)IOdim * 512];
__device__ unsigned g_OSlp[(size_t)IOdim * 512];
__device__ unsigned g_Wohp[(size_t)1024 * 1024];      // [kp][n] (2048 k rows -> 1024 kp)
__device__ unsigned g_Wolp[(size_t)1024 * 1024];
__device__ unsigned g_Wchp[(size_t)32768 * 64];       // [kp][j]
__device__ unsigned g_Wclp[(size_t)32768 * 64];
__device__ float    g_S   [(size_t)Ndim * IOdim * Sdim];   // raw scores fp32
__device__ unsigned g_Php [(size_t)Ndim * IOdim * 256];    // P packed [n][i][s/2]
__device__ unsigned g_Plp [(size_t)Ndim * IOdim * 256];
__device__ unsigned g_mixhp[(size_t)Ndim * IOdim * 512];   // [n][i][h/2]
__device__ unsigned g_mixlp[(size_t)Ndim * IOdim * 512];
__device__ unsigned g_Thp [(size_t)Ndim * IOdim * 512];    // [n][i][h/2]
__device__ unsigned g_Tlp [(size_t)Ndim * IOdim * 512];
__device__ float    g_c0p [(size_t)8 * IOdim * Hdim];
__device__ float    g_c0  [(size_t)IOdim * Hdim];
__device__ float    g_part[(size_t)128 * Ndim * IOdim];

// ---------------- bf16 split helpers ----------------
__device__ __forceinline__ unsigned bfbits(float x) {   // bf16_rn(x), fp32-aligned bits
    unsigned u = __float_as_uint(x);
    return (u + 0x7fffu + ((u >> 16) & 1u)) & 0xffff0000u;
}
__device__ __forceinline__ void split_pair(float x0, float x1,
                                           unsigned &hw, unsigned &lw) {
    const unsigned h0 = bfbits(x0), h1 = bfbits(x1);
    const float r0 = x0 - __uint_as_float(h0);
    const float r1 = x1 - __uint_as_float(h1);
    const unsigned l0 = bfbits(r0), l1 = bfbits(r1);
    hw = (h0 >> 16) | h1;
    lw = (l0 >> 16) | l1;
}
__device__ __forceinline__ float fast_tanh(float x) {
    const float e = __expf(2.0f * x);
    return __fdividef(e - 1.0f, e + 1.0f);
}
__device__ __forceinline__ void mma16(float (&d)[4], const unsigned (&a)[4],
                                      const unsigned (&b)[2]) {
    asm volatile(
        "mma.sync.aligned.m16n8k16.row.col.f32.bf16.bf16.f32 "
        "{%0,%1,%2,%3}, {%4,%5,%6,%7}, {%8,%9}, {%0,%1,%2,%3};"
        : "+f"(d[0]), "+f"(d[1]), "+f"(d[2]), "+f"(d[3])
        : "r"(a[0]), "r"(a[1]), "r"(a[2]), "r"(a[3]), "r"(b[0]), "r"(b[1]));
}

// ---------------- core GEMM: C[64,256], 8 warps x (m64,n32), K tiles of 16 ---
// MODE 0: B = packed [kp][n] global (Bh/Bl)     (outlin, c0)
// MODE 1: B = fp32 [k][n] global, split at stage (mix: states)
// MODE 2: B = fp32 [n][k] global, split at stage (scores: states)
constexpr int AST = 12;   // A smem word stride (conflict-free for frag reads)
constexpr int BKN = 264;  // B smem stride, [kp][n] modes
constexpr int BNK = 12;   // B smem stride, [n][kp] mode

template<int MODE>
__device__ __forceinline__ void gemm_core(
    const unsigned* __restrict__ Ahp, const unsigned* __restrict__ Alp, int lda_w,
    const void* __restrict__ Bp1, const void* __restrict__ Bp2, int ldb,
    int n0, int K,
    unsigned* Ash, unsigned* Asl, unsigned* Bsh, unsigned* Bsl,
    float (&acc)[4][4][4])
{
    const int tid = threadIdx.x, lane = tid & 31, warp = tid >> 5;
    const int g = lane >> 2, t = lane & 3;

    for (int k0 = 0; k0 < K; k0 += 16) {
        const int kw0 = k0 >> 1;
        __syncthreads();
        {   // A tile [64 rows][8 words]
            const int row = tid >> 2, wj = (tid & 3) * 2;
            const uint2 vh = *reinterpret_cast<const uint2*>(Ahp + (size_t)row * lda_w + kw0 + wj);
            const uint2 vl = *reinterpret_cast<const uint2*>(Alp + (size_t)row * lda_w + kw0 + wj);
            *reinterpret_cast<uint2*>(Ash + row * AST + wj) = vh;
            *reinterpret_cast<uint2*>(Asl + row * AST + wj) = vl;
        }
        if (MODE == 0) {
            const unsigned* Bh = (const unsigned*)Bp1;
            const unsigned* Bl = (const unsigned*)Bp2;
            const int kp = tid >> 5, c = (tid & 31) * 8;
            const size_t off = (size_t)(kw0 + kp) * ldb + n0 + c;
            *reinterpret_cast<uint4*>(Bsh + kp * BKN + c)     = *reinterpret_cast<const uint4*>(Bh + off);
            *reinterpret_cast<uint4*>(Bsh + kp * BKN + c + 4) = *reinterpret_cast<const uint4*>(Bh + off + 4);
            *reinterpret_cast<uint4*>(Bsl + kp * BKN + c)     = *reinterpret_cast<const uint4*>(Bl + off);
            *reinterpret_cast<uint4*>(Bsl + kp * BKN + c + 4) = *reinterpret_cast<const uint4*>(Bl + off + 4);
        } else if (MODE == 1) {
            const float* B = (const float*)Bp1;
            const int kp = tid >> 5, c = (tid & 31) * 8;
            const float* r0 = B + (size_t)(k0 + 2 * kp) * ldb + n0 + c;
            const float* r1 = r0 + ldb;
            const float4 a0 = *reinterpret_cast<const float4*>(r0);
            const float4 a1 = *reinterpret_cast<const float4*>(r0 + 4);
            const float4 b0 = *reinterpret_cast<const float4*>(r1);
            const float4 b1 = *reinterpret_cast<const float4*>(r1 + 4);
            unsigned hw[8], lw[8];
            split_pair(a0.x, b0.x, hw[0], lw[0]); split_pair(a0.y, b0.y, hw[1], lw[1]);
            split_pair(a0.z, b0.z, hw[2], lw[2]); split_pair(a0.w, b0.w, hw[3], lw[3]);
            split_pair(a1.x, b1.x, hw[4], lw[4]); split_pair(a1.y, b1.y, hw[5], lw[5]);
            split_pair(a1.z, b1.z, hw[6], lw[6]); split_pair(a1.w, b1.w, hw[7], lw[7]);
            *reinterpret_cast<uint4*>(Bsh + kp * BKN + c)     = make_uint4(hw[0], hw[1], hw[2], hw[3]);
            *reinterpret_cast<uint4*>(Bsh + kp * BKN + c + 4) = make_uint4(hw[4], hw[5], hw[6], hw[7]);
            *reinterpret_cast<uint4*>(Bsl + kp * BKN + c)     = make_uint4(lw[0], lw[1], lw[2], lw[3]);
            *reinterpret_cast<uint4*>(Bsl + kp * BKN + c + 4) = make_uint4(lw[4], lw[5], lw[6], lw[7]);
        } else {
            const float* B = (const float*)Bp1;
#pragma unroll
            for (int p = 0; p < 4; p++) {
                const int s = (tid >> 2) + 64 * p, kq = tid & 3;
                const float4 v = *reinterpret_cast<const float4*>(
                    B + (size_t)(n0 + s) * ldb + k0 + kq * 4);
                unsigned h0, l0, h1, l1;
                split_pair(v.x, v.y, h0, l0);
                split_pair(v.z, v.w, h1, l1);
                *reinterpret_cast<uint2*>(Bsh + s * BNK + kq * 2) = make_uint2(h0, h1);
                *reinterpret_cast<uint2*>(Bsl + s * BNK + kq * 2) = make_uint2(l0, l1);
            }
        }
        __syncthreads();

        unsigned Ahf[4][4], Alf[4][4];
#pragma unroll
        for (int mi = 0; mi < 4; mi++) {
            const int r = (16 * mi + g) * AST;
            Ahf[mi][0] = Ash[r + t];          Ahf[mi][1] = Ash[r + 8 * AST + t];
            Ahf[mi][2] = Ash[r + t + 4];      Ahf[mi][3] = Ash[r + 8 * AST + t + 4];
            Alf[mi][0] = Asl[r + t];          Alf[mi][1] = Asl[r + 8 * AST + t];
            Alf[mi][2] = Asl[r + t + 4];      Alf[mi][3] = Asl[r + 8 * AST + t + 4];
        }
        unsigned Bhf[4][2], Blf[4][2];
#pragma unroll
        for (int ni = 0; ni < 4; ni++) {
            const int col = warp * 32 + ni * 8 + g;
            if (MODE == 2) {
                Bhf[ni][0] = Bsh[col * BNK + t];     Bhf[ni][1] = Bsh[col * BNK + t + 4];
                Blf[ni][0] = Bsl[col * BNK + t];     Blf[ni][1] = Bsl[col * BNK + t + 4];
            } else {
                Bhf[ni][0] = Bsh[t * BKN + col];     Bhf[ni][1] = Bsh[(t + 4) * BKN + col];
                Blf[ni][0] = Bsl[t * BKN + col];     Blf[ni][1] = Bsl[(t + 4) * BKN + col];
            }
        }
        // three term groups; 16 independent MMAs between accumulator reuses
#pragma unroll
        for (int ni = 0; ni < 4; ni++)
#pragma unroll
            for (int mi = 0; mi < 4; mi++) mma16(acc[mi][ni], Ahf[mi], Bhf[ni]);
#pragma unroll
        for (int ni = 0; ni < 4; ni++)
#pragma unroll
            for (int mi = 0; mi < 4; mi++) mma16(acc[mi][ni], Ahf[mi], Blf[ni]);
#pragma unroll
        for (int ni = 0; ni < 4; ni++)
#pragma unroll
            for (int mi = 0; mi < 4; mi++) mma16(acc[mi][ni], Alf[mi], Bhf[ni]);
    }
}

// ---------------- prep kernels (run every launch; pure streaming) ----------
__global__ __launch_bounds__(256) void k_prep_os(const float* __restrict__ OS) {
    const int gid = blockIdx.x * 256 + threadIdx.x;            // 32768 words
    const float2 v = *reinterpret_cast<const float2*>(OS + 2 * (size_t)gid);
    split_pair(v.x, v.y, g_OShp[gid], g_OSlp[gid]);
}
__global__ __launch_bounds__(256) void k_prep_wo(const float* __restrict__ Wo) {
    const int gid = blockIdx.x * 256 + threadIdx.x;            // 1048576 words
    const int kp = gid >> 10, n = gid & 1023;
    const float x0 = Wo[(size_t)(2 * kp)     * 1024 + n];
    const float x1 = Wo[(size_t)(2 * kp + 1) * 1024 + n];
    split_pair(x0, x1, g_Wohp[gid], g_Wolp[gid]);
}
__global__ __launch_bounds__(256) void k_prep_wc(const float* __restrict__ Wc) {
    const int gid = blockIdx.x * 256 + threadIdx.x;            // 2097152 words
    const int kp = gid >> 6, j = gid & 63;
    const float x0 = Wc[(size_t)(2 * kp)     * 64 + j];
    const float x1 = Wc[(size_t)(2 * kp + 1) * 64 + j];
    split_pair(x0, x1, g_Wchp[gid], g_Wclp[gid]);
}

// ---------------- c0 = OS @ Wo[H:] + bo  (K-split partials) -----------------
__global__ __launch_bounds__(256, 2)
void k_c0(void)
{
    __shared__ unsigned Ash[64 * AST], Asl[64 * AST];
    __shared__ unsigned Bsh[8 * BKN],  Bsl[8 * BKN];
    const int n0 = blockIdx.x * 256, ks = blockIdx.y;          // ks: 8 x K=128
    float acc[4][4][4] = {};
    gemm_core<0>(g_OShp + ks * 64, g_OSlp + ks * 64, 512,
                 g_Wohp + (size_t)(512 + ks * 64) * 1024,
                 g_Wolp + (size_t)(512 + ks * 64) * 1024, 1024,
                 n0, 128, Ash, Asl, Bsh, Bsl, acc);
    const int lane = threadIdx.x & 31, warp = threadIdx.x >> 5;
    const int g = lane >> 2, t = lane & 3;
    float* Cp = g_c0p + (size_t)ks * IOdim * Hdim;
#pragma unroll
    for (int mi = 0; mi < 4; mi++)
#pragma unroll
        for (int ni = 0; ni < 4; ni++) {
            const int r0 = 16 * mi + g, c = n0 + warp * 32 + ni * 8 + 2 * t;
            *reinterpret_cast<float2*>(Cp + (size_t)r0 * Hdim + c) =
                make_float2(acc[mi][ni][0], acc[mi][ni][1]);
            *reinterpret_cast<float2*>(Cp + (size_t)(r0 + 8) * Hdim + c) =
                make_float2(acc[mi][ni][2], acc[mi][ni][3]);
        }
}
__global__ __launch_bounds__(256) void k_c0red(const float* __restrict__ bo) {
    const int gid = blockIdx.x * 256 + threadIdx.x;            // 65536
    float acc = bo[gid & (Hdim - 1)];
#pragma unroll
    for (int p = 0; p < 8; p++) acc += g_c0p[(size_t)p * IOdim * Hdim + gid];
    g_c0[gid] = acc;
}

// ---------------- scores = OS @ states[n]^T  -> g_S fp32 --------------------
__global__ __launch_bounds__(256, 2)
void k_scores(const float* __restrict__ states)
{
    __shared__ unsigned Ash[64 * AST], Asl[64 * AST];
    __shared__ unsigned Bsh[256 * BNK], Bsl[256 * BNK];
    const int n = blockIdx.y, n0 = blockIdx.x * 256;
    float acc[4][4][4] = {};
    gemm_core<2>(g_OShp, g_OSlp, 512,
                 states + (size_t)n * Sdim * Hdim, nullptr, Hdim,
                 n0, Hdim, Ash, Asl, Bsh, Bsl, acc);
    const int lane = threadIdx.x & 31, warp = threadIdx.x >> 5;
    const int g = lane >> 2, t = lane & 3;
    float* Cn = g_S + (size_t)n * IOdim * Sdim;
#pragma unroll
    for (int mi = 0; mi < 4; mi++)
#pragma unroll
        for (int ni = 0; ni < 4; ni++) {
            const int r0 = 16 * mi + g, c = n0 + warp * 32 + ni * 8 + 2 * t;
            *reinterpret_cast<float2*>(Cn + (size_t)r0 * Sdim + c) =
                make_float2(acc[mi][ni][0], acc[mi][ni][1]);
            *reinterpret_cast<float2*>(Cn + (size_t)(r0 + 8) * Sdim + c) =
                make_float2(acc[mi][ni][2], acc[mi][ni][3]);
        }
}

// ---------------- softmax -> packed P --------------------------------------
__global__ __launch_bounds__(256)
void k_softmax(void)
{
    const int warp = threadIdx.x >> 5, lane = threadIdx.x & 31;
    const size_t row = (size_t)blockIdx.x * 8 + warp;          // 0..4095
    const float* src = g_S + row * Sdim + lane * 16;

    float v[16];
#pragma unroll
    for (int j = 0; j < 4; j++) {
        const float4 q = *reinterpret_cast<const float4*>(src + 4 * j);
        v[4*j] = q.x; v[4*j+1] = q.y; v[4*j+2] = q.z; v[4*j+3] = q.w;
    }
    float mx = v[0];
#pragma unroll
    for (int q = 1; q < 16; q++) mx = fmaxf(mx, v[q]);
#pragma unroll
    for (int off = 16; off > 0; off >>= 1)
        mx = fmaxf(mx, __shfl_xor_sync(0xffffffffu, mx, off));
    float sum = 0.f;
#pragma unroll
    for (int q = 0; q < 16; q++) { v[q] = __expf(v[q] - mx); sum += v[q]; }
#pragma unroll
    for (int off = 16; off > 0; off >>= 1)
        sum += __shfl_xor_sync(0xffffffffu, sum, off);
    const float inv = 1.0f / sum;

    unsigned hw[8], lw[8];
#pragma unroll
    for (int j = 0; j < 8; j++) split_pair(v[2*j] * inv, v[2*j+1] * inv, hw[j], lw[j]);
    unsigned* ph = g_Php + row * 256 + lane * 8;
    unsigned* pl = g_Plp + row * 256 + lane * 8;
    *reinterpret_cast<uint4*>(ph)     = make_uint4(hw[0], hw[1], hw[2], hw[3]);
    *reinterpret_cast<uint4*>(ph + 4) = make_uint4(hw[4], hw[5], hw[6], hw[7]);
    *reinterpret_cast<uint4*>(pl)     = make_uint4(lw[0], lw[1], lw[2], lw[3]);
    *reinterpret_cast<uint4*>(pl + 4) = make_uint4(lw[4], lw[5], lw[6], lw[7]);
}

// ---------------- mix = P @ states[n] -> packed mix -------------------------
__global__ __launch_bounds__(256, 2)
void k_mix(const float* __restrict__ states)
{
    __shared__ unsigned Ash[64 * AST], Asl[64 * AST];
    __shared__ unsigned Bsh[8 * BKN],  Bsl[8 * BKN];
    const int n = blockIdx.y, n0 = blockIdx.x * 256;
    float acc[4][4][4] = {};
    gemm_core<1>(g_Php + (size_t)n * IOdim * 256, g_Plp + (size_t)n * IOdim * 256, 256,
                 states + (size_t)n * Sdim * Hdim, nullptr, Hdim,
                 n0, Sdim, Ash, Asl, Bsh, Bsl, acc);
    const int lane = threadIdx.x & 31, warp = threadIdx.x >> 5;
    const int g = lane >> 2, t = lane & 3;
    unsigned* Mh = g_mixhp + (size_t)n * IOdim * 512;
    unsigned* Ml = g_mixlp + (size_t)n * IOdim * 512;
#pragma unroll
    for (int mi = 0; mi < 4; mi++)
#pragma unroll
        for (int ni = 0; ni < 4; ni++) {
            const int r0 = 16 * mi + g;
            const int wc = ((n0 + warp * 32 + ni * 8) >> 1) + t;
            unsigned h, l;
            split_pair(acc[mi][ni][0], acc[mi][ni][1], h, l);
            Mh[(size_t)r0 * 512 + wc] = h;  Ml[(size_t)r0 * 512 + wc] = l;
            split_pair(acc[mi][ni][2], acc[mi][ni][3], h, l);
            Mh[(size_t)(r0 + 8) * 512 + wc] = h;  Ml[(size_t)(r0 + 8) * 512 + wc] = l;
        }
}

// ---------------- t = tanh(mix @ Wo[:H] + c0) -> packed T --------------------
__global__ __launch_bounds__(256, 2)
void k_outlin(void)
{
    __shared__ unsigned Ash[64 * AST], Asl[64 * AST];
    __shared__ unsigned Bsh[8 * BKN],  Bsl[8 * BKN];
    const int n = blockIdx.y, n0 = blockIdx.x * 256;
    float acc[4][4][4] = {};
    gemm_core<0>(g_mixhp + (size_t)n * IOdim * 512, g_mixlp + (size_t)n * IOdim * 512, 512,
                 g_Wohp, g_Wolp, 1024,
                 n0, Hdim, Ash, Asl, Bsh, Bsl, acc);
    const int lane = threadIdx.x & 31, warp = threadIdx.x >> 5;
    const int g = lane >> 2, t = lane & 3;
    unsigned* Th = g_Thp + (size_t)n * IOdim * 512;
    unsigned* Tl = g_Tlp + (size_t)n * IOdim * 512;
#pragma unroll
    for (int mi = 0; mi < 4; mi++)
#pragma unroll
        for (int ni = 0; ni < 4; ni++) {
            const int r0 = 16 * mi + g, c = n0 + warp * 32 + ni * 8 + 2 * t;
            const int wc = c >> 1;
            const float2 b0 = *reinterpret_cast<const float2*>(g_c0 + (size_t)r0 * Hdim + c);
            const float2 b1 = *reinterpret_cast<const float2*>(g_c0 + (size_t)(r0 + 8) * Hdim + c);
            unsigned h, l;
            split_pair(fast_tanh(acc[mi][ni][0] + b0.x),
                       fast_tanh(acc[mi][ni][1] + b0.y), h, l);
            Th[(size_t)r0 * 512 + wc] = h;  Tl[(size_t)r0 * 512 + wc] = l;
            split_pair(fast_tanh(acc[mi][ni][2] + b1.x),
                       fast_tanh(acc[mi][ni][3] + b1.y), h, l);
            Th[(size_t)(r0 + 8) * 512 + wc] = h;  Tl[(size_t)(r0 + 8) * 512 + wc] = l;
        }
}

// ---------------- logits: T @ Wc (bf16 3-term, K-split) ----------------------
__global__ __launch_bounds__(256, 2)
void k_logits(void)
{
    __shared__ unsigned Ash[64 * AST], Asl[64 * AST];
    __shared__ unsigned Bsh[8 * 72],   Bsl[8 * 72];
    const int chunk = blockIdx.x;                 // 128 chunks of K=512
    const unsigned* Ahp = g_Thp + (size_t)chunk * 256;   // lda_w = 32768
    const unsigned* Alp = g_Tlp + (size_t)chunk * 256;
    const unsigned* Bhp = g_Wchp + (size_t)chunk * 256 * 64;
    const unsigned* Blp = g_Wclp + (size_t)chunk * 256 * 64;

    const int tid = threadIdx.x, lane = tid & 31, warp = tid >> 5;
    const int g = lane >> 2, t = lane & 3;
    float acc[4][4] = {};

    for (int k0 = 0; k0 < 512; k0 += 16) {
        const int kw0 = k0 >> 1;
        __syncthreads();
        {
            const int row = tid >> 2, wj = (tid & 3) * 2;
            *reinterpret_cast<uint2*>(Ash + row * AST + wj) =
                *reinterpret_cast<const uint2*>(Ahp + (size_t)row * 32768 + kw0 + wj);
            *reinterpret_cast<uint2*>(Asl + row * AST + wj) =
                *reinterpret_cast<const uint2*>(Alp + (size_t)row * 32768 + kw0 + wj);
        }
        {
            const int kp = tid >> 5, c = (tid & 31) * 2;
            *reinterpret_cast<uint2*>(Bsh + kp * 72 + c) =
                *reinterpret_cast<const uint2*>(Bhp + (size_t)(kw0 + kp) * 64 + c);
            *reinterpret_cast<uint2*>(Bsl + kp * 72 + c) =
                *reinterpret_cast<const uint2*>(Blp + (size_t)(kw0 + kp) * 64 + c);
        }
        __syncthreads();

        unsigned Ahf[4][4], Alf[4][4];
#pragma unroll
        for (int mi = 0; mi < 4; mi++) {
            const int r = (16 * mi + g) * AST;
            Ahf[mi][0] = Ash[r + t];        Ahf[mi][1] = Ash[r + 8 * AST + t];
            Ahf[mi][2] = Ash[r + t + 4];    Ahf[mi][3] = Ash[r + 8 * AST + t + 4];
            Alf[mi][0] = Asl[r + t];        Alf[mi][1] = Asl[r + 8 * AST + t];
            Alf[mi][2] = Asl[r + t + 4];    Alf[mi][3] = Asl[r + 8 * AST + t + 4];
        }
        const int col = warp * 8 + g;
        unsigned bh[2] = { Bsh[t * 72 + col], Bsh[(t + 4) * 72 + col] };
        unsigned bl[2] = { Bsl[t * 72 + col], Bsl[(t + 4) * 72 + col] };
#pragma unroll
        for (int mi = 0; mi < 4; mi++) mma16(acc[mi], Ahf[mi], bh);
#pragma unroll
        for (int mi = 0; mi < 4; mi++) mma16(acc[mi], Ahf[mi], bl);
#pragma unroll
        for (int mi = 0; mi < 4; mi++) mma16(acc[mi], Alf[mi], bh);
    }
    float* Cp = g_part + (size_t)chunk * Ndim * IOdim;
#pragma unroll
    for (int mi = 0; mi < 4; mi++) {
        const int r0 = 16 * mi + g, c = warp * 8 + 2 * t;
        *reinterpret_cast<float2*>(Cp + (size_t)r0 * IOdim + c) =
            make_float2(acc[mi][0], acc[mi][1]);
        *reinterpret_cast<float2*>(Cp + (size_t)(r0 + 8) * IOdim + c) =
            make_float2(acc[mi][2], acc[mi][3]);
    }
}

__global__ __launch_bounds__(256)
void k_reduce(const float* __restrict__ bc, float* __restrict__ out)
{
    const int gid = blockIdx.x * 256 + threadIdx.x;
    float acc = bc[gid & 63];
#pragma unroll 8
    for (int ch = 0; ch < 128; ch++) acc += g_part[(size_t)ch * 4096 + gid];
    out[gid] = acc;
}

// ===========================================================================
extern "C" void kernel_launch(void* const* d_in, const int* in_sizes, int n_in,
                              void* d_out, int out_size)
{
    const float* states = (const float*)d_in[0];  // [64, 512, 1024]
    const float* OS     = (const float*)d_in[1];  // [64, 1024]
    const float* Wo     = (const float*)d_in[2];  // [2048, 1024]
    const float* bo     = (const float*)d_in[3];  // [1024]
    const float* Wc     = (const float*)d_in[4];  // [65536, 64]
    const float* bc     = (const float*)d_in[5];  // [64]
    float* out = (float*)d_out;                   // [64, 64]

    k_prep_os<<<128,  256>>>(OS);
    k_prep_wo<<<4096, 256>>>(Wo);
    k_prep_wc<<<8192, 256>>>(Wc);
    k_c0     <<<dim3(4, 8),  256>>>();
    k_c0red  <<<256,  256>>>(bo);
    k_scores <<<dim3(2, 64), 256>>>(states);
    k_softmax<<<512,  256>>>();
    k_mix    <<<dim3(4, 64), 256>>>(states);
    k_outlin <<<dim3(4, 64), 256>>>();
    k_logits <<<128,  256>>>();
    k_reduce <<<16,   256>>>(bc, out);
}

// round 4
// speedup vs baseline: 2.1631x; 1.2722x over previous
#include <cuda_runtime.h>
#include <math.h>

#define Ndim  64
#define Sdim  512
#define Hdim  1024
#define IOdim 64

// ---------------- scratch (no allocations allowed) ----------------
// "hp/lp" arrays are bf16x2 words: word w packs k=2w (lo16), k=2w+1 (hi16);
// float(hp)+float(lp) reproduces fp32 to ~2^-18.
__device__ unsigned g_OShp[(size_t)IOdim * 512];
__device__ unsigned g_OSlp[(size_t)IOdim * 512];
__device__ unsigned g_Wohp[(size_t)1024 * 1024];      // [kp][n]
__device__ unsigned g_Wolp[(size_t)1024 * 1024];
__device__ unsigned g_Wchp[(size_t)32768 * 64];       // [kp][j]
__device__ unsigned g_Wclp[(size_t)32768 * 64];
__device__ float    g_S   [(size_t)Ndim * IOdim * Sdim];
__device__ unsigned g_Php [(size_t)Ndim * IOdim * 256];
__device__ unsigned g_Plp [(size_t)Ndim * IOdim * 256];
__device__ unsigned g_mixhp[(size_t)Ndim * IOdim * 512];
__device__ unsigned g_mixlp[(size_t)Ndim * IOdim * 512];
__device__ unsigned g_Thp [(size_t)Ndim * IOdim * 512];
__device__ unsigned g_Tlp [(size_t)Ndim * IOdim * 512];
__device__ float    g_c0p [(size_t)16 * IOdim * Hdim];
__device__ float    g_c0  [(size_t)IOdim * Hdim];
__device__ float    g_part[(size_t)128 * Ndim * IOdim];

// ---------------- helpers ----------------
__device__ __forceinline__ unsigned bfbits(float x) {
    unsigned u = __float_as_uint(x);
    return (u + 0x7fffu + ((u >> 16) & 1u)) & 0xffff0000u;
}
__device__ __forceinline__ void split_pair(float x0, float x1,
                                           unsigned &hw, unsigned &lw) {
    const unsigned h0 = bfbits(x0), h1 = bfbits(x1);
    const unsigned l0 = bfbits(x0 - __uint_as_float(h0));
    const unsigned l1 = bfbits(x1 - __uint_as_float(h1));
    hw = (h0 >> 16) | h1;
    lw = (l0 >> 16) | l1;
}
__device__ __forceinline__ unsigned pack_bf(float x0, float x1) {
    return (bfbits(x0) >> 16) | bfbits(x1);
}
__device__ __forceinline__ float fast_tanh(float x) {
    const float e = __expf(2.0f * x);
    return __fdividef(e - 1.0f, e + 1.0f);
}
__device__ __forceinline__ void mma16(float (&d)[4], const unsigned (&a)[4],
                                      const unsigned (&b)[2]) {
    asm volatile(
        "mma.sync.aligned.m16n8k16.row.col.f32.bf16.bf16.f32 "
        "{%0,%1,%2,%3}, {%4,%5,%6,%7}, {%8,%9}, {%0,%1,%2,%3};"
        : "+f"(d[0]), "+f"(d[1]), "+f"(d[2]), "+f"(d[3])
        : "r"(a[0]), "r"(a[1]), "r"(a[2]), "r"(a[3]), "r"(b[0]), "r"(b[1]));
}
__device__ __forceinline__ void cpa16(unsigned* smem_ptr, const void* gptr) {
    unsigned s = (unsigned)__cvta_generic_to_shared(smem_ptr);
    asm volatile("cp.async.ca.shared.global [%0], [%1], 16;" :: "r"(s), "l"(gptr));
}
#define CP_COMMIT() asm volatile("cp.async.commit_group;")
#define CP_WAIT1()  asm volatile("cp.async.wait_group 1;")
#define CP_WAIT0()  asm volatile("cp.async.wait_group 0;")

constexpr int AST = 12;   // A smem word stride
constexpr int BKN = 264;  // B smem stride for [kp][n]
constexpr int BNK = 12;   // B smem stride for [n][kp]

// ---------------------------------------------------------------------------
// Pipelined 64x256 GEMM core.
// MODE 0: A packed (cp.async x2 terms, double buf), B packed (cp.async x2, double buf), 3-term
// MODE 1: A packed (cp.async x2, double buf), B fp32 [k][n] (reg-pipelined, split at STS), 3-term
// MODE 2: A packed hp only (cp.async, double buf), B fp32 [n][k] (reg-pipelined, bf16), 1-term
// ---------------------------------------------------------------------------
template<int MODE>
__device__ __forceinline__ void gemm_pipe(
    const unsigned* __restrict__ Ahp, const unsigned* __restrict__ Alp, int lda_w,
    const void* __restrict__ Bp1, const void* __restrict__ Bp2, int ldb,
    int n0, int K,
    unsigned* AshB, unsigned* AslB, unsigned* BshB, unsigned* BslB,
    float (&acc)[4][4][4])
{
    const int tid = threadIdx.x, lane = tid & 31, warp = tid >> 5;
    const int g = lane >> 2, t = lane & 3;
    const int nkt = K >> 4;

    float4 br[4];   // reg pipeline for MODE 1/2

    // ---- staging helpers ----
    auto stageA = [&](int st, int kt) {
        const int kw0 = kt << 3;
        if (MODE == 2) {
            if (tid < 128) {
                const int row = tid >> 1, wj = (tid & 1) * 4;
                cpa16(AshB + st * 64 * AST + row * AST + wj,
                      Ahp + (size_t)row * lda_w + kw0 + wj);
            }
        } else {
            const int row = (tid & 127) >> 1, wj = (tid & 1) * 4;
            const unsigned* src = (tid < 128 ? Ahp : Alp) + (size_t)row * lda_w + kw0 + wj;
            unsigned* dst = (tid < 128 ? AshB : AslB) + st * 64 * AST + row * AST + wj;
            cpa16(dst, src);
        }
    };
    auto stageB0 = [&](int st, int kt) {
        const int kw0 = kt << 3;
        const unsigned* Bh = (const unsigned*)Bp1;
        const unsigned* Bl = (const unsigned*)Bp2;
#pragma unroll
        for (int j = 0; j < 2; j++) {
            const int ch = tid * 2 + j;               // 0..511
            const int row = ch >> 6, c4 = (ch & 63) * 4;
            cpa16(BshB + st * 8 * BKN + row * BKN + c4,
                  Bh + (size_t)(kw0 + row) * ldb + n0 + c4);
            cpa16(BslB + st * 8 * BKN + row * BKN + c4,
                  Bl + (size_t)(kw0 + row) * ldb + n0 + c4);
        }
    };
    auto ldgB1 = [&](int kt) {
        const float* B = (const float*)Bp1;
        const int k0 = kt << 4;
        const int kp = tid >> 5, c = (tid & 31) * 8;
        const float* r0 = B + (size_t)(k0 + 2 * kp) * ldb + n0 + c;
        br[0] = *reinterpret_cast<const float4*>(r0);
        br[1] = *reinterpret_cast<const float4*>(r0 + 4);
        br[2] = *reinterpret_cast<const float4*>(r0 + ldb);
        br[3] = *reinterpret_cast<const float4*>(r0 + ldb + 4);
    };
    auto stsB1 = [&]() {
        const int kp = tid >> 5, c = (tid & 31) * 8;
        unsigned hw[8], lw[8];
        split_pair(br[0].x, br[2].x, hw[0], lw[0]);
        split_pair(br[0].y, br[2].y, hw[1], lw[1]);
        split_pair(br[0].z, br[2].z, hw[2], lw[2]);
        split_pair(br[0].w, br[2].w, hw[3], lw[3]);
        split_pair(br[1].x, br[3].x, hw[4], lw[4]);
        split_pair(br[1].y, br[3].y, hw[5], lw[5]);
        split_pair(br[1].z, br[3].z, hw[6], lw[6]);
        split_pair(br[1].w, br[3].w, hw[7], lw[7]);
        *reinterpret_cast<uint4*>(BshB + kp * BKN + c)     = make_uint4(hw[0], hw[1], hw[2], hw[3]);
        *reinterpret_cast<uint4*>(BshB + kp * BKN + c + 4) = make_uint4(hw[4], hw[5], hw[6], hw[7]);
        *reinterpret_cast<uint4*>(BslB + kp * BKN + c)     = make_uint4(lw[0], lw[1], lw[2], lw[3]);
        *reinterpret_cast<uint4*>(BslB + kp * BKN + c + 4) = make_uint4(lw[4], lw[5], lw[6], lw[7]);
    };
    auto ldgB2 = [&](int kt) {
        const float* B = (const float*)Bp1;
        const int k0 = kt << 4, kq = tid & 3;
#pragma unroll
        for (int p = 0; p < 4; p++) {
            const int s = (tid >> 2) + 64 * p;
            br[p] = *reinterpret_cast<const float4*>(
                B + (size_t)(n0 + s) * ldb + k0 + kq * 4);
        }
    };
    auto stsB2 = [&]() {
        const int kq = tid & 3;
#pragma unroll
        for (int p = 0; p < 4; p++) {
            const int s = (tid >> 2) + 64 * p;
            *reinterpret_cast<uint2*>(BshB + s * BNK + kq * 2) =
                make_uint2(pack_bf(br[p].x, br[p].y), pack_bf(br[p].z, br[p].w));
        }
    };

    // ---- prologue ----
    stageA(0, 0);
    if (MODE == 0) stageB0(0, 0);
    CP_COMMIT();
    if (MODE == 1) ldgB1(0);
    if (MODE == 2) ldgB2(0);

    for (int kt = 0; kt < nkt; kt++) {
        const int st = kt & 1;
        __syncthreads();
        if (MODE == 1) stsB1();
        if (MODE == 2) stsB2();
        if (kt + 1 < nkt) {
            stageA(st ^ 1, kt + 1);
            if (MODE == 0) stageB0(st ^ 1, kt + 1);
            CP_COMMIT();
            if (MODE == 1) ldgB1(kt + 1);
            if (MODE == 2) ldgB2(kt + 1);
            CP_WAIT1();
        } else {
            CP_WAIT0();
        }
        __syncthreads();

        const unsigned* Ash = AshB + st * 64 * AST;
        const unsigned* Asl = AslB + st * 64 * AST;
        const unsigned* Bsc = (MODE == 0) ? BshB + st * 8 * BKN : BshB;
        const unsigned* Bsd = (MODE == 0) ? BslB + st * 8 * BKN : BslB;

        unsigned Ahf[4][4];
#pragma unroll
        for (int mi = 0; mi < 4; mi++) {
            const int r = (16 * mi + g) * AST;
            Ahf[mi][0] = Ash[r + t];        Ahf[mi][1] = Ash[r + 8 * AST + t];
            Ahf[mi][2] = Ash[r + t + 4];    Ahf[mi][3] = Ash[r + 8 * AST + t + 4];
        }
        unsigned Bhf[4][2];
#pragma unroll
        for (int ni = 0; ni < 4; ni++) {
            const int col = warp * 32 + ni * 8 + g;
            if (MODE == 2) {
                Bhf[ni][0] = Bsc[col * BNK + t];   Bhf[ni][1] = Bsc[col * BNK + t + 4];
            } else {
                Bhf[ni][0] = Bsc[t * BKN + col];   Bhf[ni][1] = Bsc[(t + 4) * BKN + col];
            }
        }
#pragma unroll
        for (int ni = 0; ni < 4; ni++)
#pragma unroll
            for (int mi = 0; mi < 4; mi++) mma16(acc[mi][ni], Ahf[mi], Bhf[ni]);

        if (MODE != 2) {
            unsigned Alf[4][4], Blf[4][2];
#pragma unroll
            for (int mi = 0; mi < 4; mi++) {
                const int r = (16 * mi + g) * AST;
                Alf[mi][0] = Asl[r + t];        Alf[mi][1] = Asl[r + 8 * AST + t];
                Alf[mi][2] = Asl[r + t + 4];    Alf[mi][3] = Asl[r + 8 * AST + t + 4];
            }
#pragma unroll
            for (int ni = 0; ni < 4; ni++) {
                const int col = warp * 32 + ni * 8 + g;
                Blf[ni][0] = Bsd[t * BKN + col];   Blf[ni][1] = Bsd[(t + 4) * BKN + col];
            }
#pragma unroll
            for (int ni = 0; ni < 4; ni++)
#pragma unroll
                for (int mi = 0; mi < 4; mi++) mma16(acc[mi][ni], Ahf[mi], Blf[ni]);
#pragma unroll
            for (int ni = 0; ni < 4; ni++)
#pragma unroll
                for (int mi = 0; mi < 4; mi++) mma16(acc[mi][ni], Alf[mi], Bhf[ni]);
        }
    }
}

// ---------------- prep kernels ----------------
__global__ __launch_bounds__(256) void k_prep_os(const float* __restrict__ OS) {
    const int gid = blockIdx.x * 256 + threadIdx.x;
    const float2 v = *reinterpret_cast<const float2*>(OS + 2 * (size_t)gid);
    split_pair(v.x, v.y, g_OShp[gid], g_OSlp[gid]);
}
__global__ __launch_bounds__(256) void k_prep_wo(const float* __restrict__ Wo) {
    const int gid = blockIdx.x * 256 + threadIdx.x;
    const int kp = gid >> 10, n = gid & 1023;
    split_pair(Wo[(size_t)(2 * kp) * 1024 + n], Wo[(size_t)(2 * kp + 1) * 1024 + n],
               g_Wohp[gid], g_Wolp[gid]);
}
__global__ __launch_bounds__(256) void k_prep_wc(const float* __restrict__ Wc) {
    const int gid = blockIdx.x * 256 + threadIdx.x;
    const int kp = gid >> 6, j = gid & 63;
    split_pair(Wc[(size_t)(2 * kp) * 64 + j], Wc[(size_t)(2 * kp + 1) * 64 + j],
               g_Wchp[gid], g_Wclp[gid]);
}

// ---------------- c0 = OS @ Wo[H:] + bo  (16-way K-split) -------------------
__global__ __launch_bounds__(256, 2)
void k_c0(void)
{
    __shared__ unsigned Ash[2 * 64 * AST], Asl[2 * 64 * AST];
    __shared__ unsigned Bsh[2 * 8 * BKN],  Bsl[2 * 8 * BKN];
    const int n0 = blockIdx.x * 256, ks = blockIdx.y;      // 16 slices of K=64
    float acc[4][4][4] = {};
    gemm_pipe<0>(g_OShp + ks * 32, g_OSlp + ks * 32, 512,
                 g_Wohp + (size_t)(512 + ks * 32) * 1024,
                 g_Wolp + (size_t)(512 + ks * 32) * 1024, 1024,
                 n0, 64, Ash, Asl, Bsh, Bsl, acc);
    const int lane = threadIdx.x & 31, warp = threadIdx.x >> 5;
    const int g = lane >> 2, t = lane & 3;
    float* Cp = g_c0p + (size_t)ks * IOdim * Hdim;
#pragma unroll
    for (int mi = 0; mi < 4; mi++)
#pragma unroll
        for (int ni = 0; ni < 4; ni++) {
            const int r0 = 16 * mi + g, c = n0 + warp * 32 + ni * 8 + 2 * t;
            *reinterpret_cast<float2*>(Cp + (size_t)r0 * Hdim + c) =
                make_float2(acc[mi][ni][0], acc[mi][ni][1]);
            *reinterpret_cast<float2*>(Cp + (size_t)(r0 + 8) * Hdim + c) =
                make_float2(acc[mi][ni][2], acc[mi][ni][3]);
        }
}
__global__ __launch_bounds__(256) void k_c0red(const float* __restrict__ bo) {
    const int gid = blockIdx.x * 256 + threadIdx.x;
    float acc = bo[gid & (Hdim - 1)];
#pragma unroll
    for (int p = 0; p < 16; p++) acc += g_c0p[(size_t)p * IOdim * Hdim + gid];
    g_c0[gid] = acc;
}

// ---------------- scores = OS @ states[n]^T (1-term bf16) -------------------
__global__ __launch_bounds__(256, 2)
void k_scores(const float* __restrict__ states)
{
    __shared__ unsigned Ash[2 * 64 * AST];
    __shared__ unsigned Bsh[256 * BNK];
    const int n = blockIdx.y, n0 = blockIdx.x * 256;
    float acc[4][4][4] = {};
    gemm_pipe<2>(g_OShp, nullptr, 512,
                 states + (size_t)n * Sdim * Hdim, nullptr, Hdim,
                 n0, Hdim, Ash, Ash, Bsh, Bsh, acc);
    const int lane = threadIdx.x & 31, warp = threadIdx.x >> 5;
    const int g = lane >> 2, t = lane & 3;
    float* Cn = g_S + (size_t)n * IOdim * Sdim;
#pragma unroll
    for (int mi = 0; mi < 4; mi++)
#pragma unroll
        for (int ni = 0; ni < 4; ni++) {
            const int r0 = 16 * mi + g, c = n0 + warp * 32 + ni * 8 + 2 * t;
            *reinterpret_cast<float2*>(Cn + (size_t)r0 * Sdim + c) =
                make_float2(acc[mi][ni][0], acc[mi][ni][1]);
            *reinterpret_cast<float2*>(Cn + (size_t)(r0 + 8) * Sdim + c) =
                make_float2(acc[mi][ni][2], acc[mi][ni][3]);
        }
}

// ---------------- softmax -> packed P --------------------------------------
__global__ __launch_bounds__(256)
void k_softmax(void)
{
    const int warp = threadIdx.x >> 5, lane = threadIdx.x & 31;
    const size_t row = (size_t)blockIdx.x * 8 + warp;
    const float* src = g_S + row * Sdim + lane * 16;
    float v[16];
#pragma unroll
    for (int j = 0; j < 4; j++) {
        const float4 q = *reinterpret_cast<const float4*>(src + 4 * j);
        v[4*j] = q.x; v[4*j+1] = q.y; v[4*j+2] = q.z; v[4*j+3] = q.w;
    }
    float mx = v[0];
#pragma unroll
    for (int q = 1; q < 16; q++) mx = fmaxf(mx, v[q]);
#pragma unroll
    for (int off = 16; off > 0; off >>= 1)
        mx = fmaxf(mx, __shfl_xor_sync(0xffffffffu, mx, off));
    float sum = 0.f;
#pragma unroll
    for (int q = 0; q < 16; q++) { v[q] = __expf(v[q] - mx); sum += v[q]; }
#pragma unroll
    for (int off = 16; off > 0; off >>= 1)
        sum += __shfl_xor_sync(0xffffffffu, sum, off);
    const float inv = 1.0f / sum;
    unsigned hw[8], lw[8];
#pragma unroll
    for (int j = 0; j < 8; j++) split_pair(v[2*j] * inv, v[2*j+1] * inv, hw[j], lw[j]);
    unsigned* ph = g_Php + row * 256 + lane * 8;
    unsigned* pl = g_Plp + row * 256 + lane * 8;
    *reinterpret_cast<uint4*>(ph)     = make_uint4(hw[0], hw[1], hw[2], hw[3]);
    *reinterpret_cast<uint4*>(ph + 4) = make_uint4(hw[4], hw[5], hw[6], hw[7]);
    *reinterpret_cast<uint4*>(pl)     = make_uint4(lw[0], lw[1], lw[2], lw[3]);
    *reinterpret_cast<uint4*>(pl + 4) = make_uint4(lw[4], lw[5], lw[6], lw[7]);
}

// ---------------- mix = P @ states[n] -> packed mix -------------------------
__global__ __launch_bounds__(256, 2)
void k_mix(const float* __restrict__ states)
{
    __shared__ unsigned Ash[2 * 64 * AST], Asl[2 * 64 * AST];
    __shared__ unsigned Bsh[8 * BKN],      Bsl[8 * BKN];
    const int n = blockIdx.y, n0 = blockIdx.x * 256;
    float acc[4][4][4] = {};
    gemm_pipe<1>(g_Php + (size_t)n * IOdim * 256, g_Plp + (size_t)n * IOdim * 256, 256,
                 states + (size_t)n * Sdim * Hdim, nullptr, Hdim,
                 n0, Sdim, Ash, Asl, Bsh, Bsl, acc);
    const int lane = threadIdx.x & 31, warp = threadIdx.x >> 5;
    const int g = lane >> 2, t = lane & 3;
    unsigned* Mh = g_mixhp + (size_t)n * IOdim * 512;
    unsigned* Ml = g_mixlp + (size_t)n * IOdim * 512;
#pragma unroll
    for (int mi = 0; mi < 4; mi++)
#pragma unroll
        for (int ni = 0; ni < 4; ni++) {
            const int r0 = 16 * mi + g;
            const int wc = ((n0 + warp * 32 + ni * 8) >> 1) + t;
            unsigned h, l;
            split_pair(acc[mi][ni][0], acc[mi][ni][1], h, l);
            Mh[(size_t)r0 * 512 + wc] = h;  Ml[(size_t)r0 * 512 + wc] = l;
            split_pair(acc[mi][ni][2], acc[mi][ni][3], h, l);
            Mh[(size_t)(r0 + 8) * 512 + wc] = h;  Ml[(size_t)(r0 + 8) * 512 + wc] = l;
        }
}

// ---------------- t = tanh(mix @ Wo[:H] + c0) -> packed T --------------------
__global__ __launch_bounds__(256, 2)
void k_outlin(void)
{
    __shared__ unsigned Ash[2 * 64 * AST], Asl[2 * 64 * AST];
    __shared__ unsigned Bsh[2 * 8 * BKN],  Bsl[2 * 8 * BKN];
    const int n = blockIdx.y, n0 = blockIdx.x * 256;
    float acc[4][4][4] = {};
    gemm_pipe<0>(g_mixhp + (size_t)n * IOdim * 512, g_mixlp + (size_t)n * IOdim * 512, 512,
                 g_Wohp, g_Wolp, 1024, n0, Hdim, Ash, Asl, Bsh, Bsl, acc);
    const int lane = threadIdx.x & 31, warp = threadIdx.x >> 5;
    const int g = lane >> 2, t = lane & 3;
    unsigned* Th = g_Thp + (size_t)n * IOdim * 512;
    unsigned* Tl = g_Tlp + (size_t)n * IOdim * 512;
#pragma unroll
    for (int mi = 0; mi < 4; mi++)
#pragma unroll
        for (int ni = 0; ni < 4; ni++) {
            const int r0 = 16 * mi + g, c = n0 + warp * 32 + ni * 8 + 2 * t;
            const int wc = c >> 1;
            const float2 b0 = *reinterpret_cast<const float2*>(g_c0 + (size_t)r0 * Hdim + c);
            const float2 b1 = *reinterpret_cast<const float2*>(g_c0 + (size_t)(r0 + 8) * Hdim + c);
            unsigned h, l;
            split_pair(fast_tanh(acc[mi][ni][0] + b0.x),
                       fast_tanh(acc[mi][ni][1] + b0.y), h, l);
            Th[(size_t)r0 * 512 + wc] = h;  Tl[(size_t)r0 * 512 + wc] = l;
            split_pair(fast_tanh(acc[mi][ni][2] + b1.x),
                       fast_tanh(acc[mi][ni][3] + b1.y), h, l);
            Th[(size_t)(r0 + 8) * 512 + wc] = h;  Tl[(size_t)(r0 + 8) * 512 + wc] = l;
        }
}

// ---------------- logits: T @ Wc (3-term, pipelined) -------------------------
constexpr int BKL = 72;
__global__ __launch_bounds__(256, 2)
void k_logits(void)
{
    __shared__ unsigned Ash[2 * 64 * AST], Asl[2 * 64 * AST];
    __shared__ unsigned Bsh[2 * 8 * BKL],  Bsl[2 * 8 * BKL];
    const int chunk = blockIdx.x;
    const unsigned* Ahp = g_Thp + (size_t)chunk * 256;
    const unsigned* Alp = g_Tlp + (size_t)chunk * 256;
    const unsigned* Bhp = g_Wchp + (size_t)chunk * 256 * 64;
    const unsigned* Blp = g_Wclp + (size_t)chunk * 256 * 64;

    const int tid = threadIdx.x, lane = tid & 31, warp = tid >> 5;
    const int g = lane >> 2, t = lane & 3;
    float acc[4][4] = {};

    auto stage = [&](int st, int kt) {
        const int kw0 = kt << 3;
        {   // A
            const int row = (tid & 127) >> 1, wj = (tid & 1) * 4;
            const unsigned* src = (tid < 128 ? Ahp : Alp) + (size_t)row * 32768 + kw0 + wj;
            unsigned* dst = (tid < 128 ? Ash : Asl) + st * 64 * AST + row * AST + wj;
            cpa16(dst, src);
        }
        {   // B
            const int ch = tid & 127;
            const int row = ch >> 4, c4 = (ch & 15) * 4;
            const unsigned* src = (tid < 128 ? Bhp : Blp) + (size_t)(kw0 + row) * 64 + c4;
            unsigned* dst = (tid < 128 ? Bsh : Bsl) + st * 8 * BKL + row * BKL + c4;
            cpa16(dst, src);
        }
    };

    stage(0, 0); CP_COMMIT();
    const int nkt = 32;
    for (int kt = 0; kt < nkt; kt++) {
        const int st = kt & 1;
        __syncthreads();
        if (kt + 1 < nkt) { stage(st ^ 1, kt + 1); CP_COMMIT(); CP_WAIT1(); }
        else              { CP_WAIT0(); }
        __syncthreads();

        const unsigned* As = Ash + st * 64 * AST;
        const unsigned* Al = Asl + st * 64 * AST;
        const unsigned* Bs = Bsh + st * 8 * BKL;
        const unsigned* Bl = Bsl + st * 8 * BKL;

        unsigned Ahf[4][4], Alf[4][4];
#pragma unroll
        for (int mi = 0; mi < 4; mi++) {
            const int r = (16 * mi + g) * AST;
            Ahf[mi][0] = As[r + t];        Ahf[mi][1] = As[r + 8 * AST + t];
            Ahf[mi][2] = As[r + t + 4];    Ahf[mi][3] = As[r + 8 * AST + t + 4];
            Alf[mi][0] = Al[r + t];        Alf[mi][1] = Al[r + 8 * AST + t];
            Alf[mi][2] = Al[r + t + 4];    Alf[mi][3] = Al[r + 8 * AST + t + 4];
        }
        const int col = warp * 8 + g;
        unsigned bh[2] = { Bs[t * BKL + col], Bs[(t + 4) * BKL + col] };
        unsigned bl[2] = { Bl[t * BKL + col], Bl[(t + 4) * BKL + col] };
#pragma unroll
        for (int mi = 0; mi < 4; mi++) mma16(acc[mi], Ahf[mi], bh);
#pragma unroll
        for (int mi = 0; mi < 4; mi++) mma16(acc[mi], Ahf[mi], bl);
#pragma unroll
        for (int mi = 0; mi < 4; mi++) mma16(acc[mi], Alf[mi], bh);
    }
    float* Cp = g_part + (size_t)chunk * Ndim * IOdim;
#pragma unroll
    for (int mi = 0; mi < 4; mi++) {
        const int r0 = 16 * mi + g, c = warp * 8 + 2 * t;
        *reinterpret_cast<float2*>(Cp + (size_t)r0 * IOdim + c) =
            make_float2(acc[mi][0], acc[mi][1]);
        *reinterpret_cast<float2*>(Cp + (size_t)(r0 + 8) * IOdim + c) =
            make_float2(acc[mi][2], acc[mi][3]);
    }
}

__global__ __launch_bounds__(256)
void k_reduce(const float* __restrict__ bc, float* __restrict__ out)
{
    const int gid = blockIdx.x * 256 + threadIdx.x;
    float acc = bc[gid & 63];
#pragma unroll 8
    for (int ch = 0; ch < 128; ch++) acc += g_part[(size_t)ch * 4096 + gid];
    out[gid] = acc;
}

// ===========================================================================
extern "C" void kernel_launch(void* const* d_in, const int* in_sizes, int n_in,
                              void* d_out, int out_size)
{
    const float* states = (const float*)d_in[0];
    const float* OS     = (const float*)d_in[1];
    const float* Wo     = (const float*)d_in[2];
    const float* bo     = (const float*)d_in[3];
    const float* Wc     = (const float*)d_in[4];
    const float* bc     = (const float*)d_in[5];
    float* out = (float*)d_out;

    k_prep_os<<<128,  256>>>(OS);
    k_prep_wo<<<4096, 256>>>(Wo);
    k_prep_wc<<<8192, 256>>>(Wc);
    k_c0     <<<dim3(4, 16), 256>>>();
    k_c0red  <<<256,  256>>>(bo);
    k_scores <<<dim3(2, 64), 256>>>(states);
    k_softmax<<<512,  256>>>();
    k_mix    <<<dim3(4, 64), 256>>>(states);
    k_outlin <<<dim3(4, 64), 256>>>();
    k_logits <<<128,  256>>>();
    k_reduce <<<16,   256>>>(bc, out);
}

// round 5
// speedup vs baseline: 2.3310x; 1.0776x over previous
#include <cuda_runtime.h>
#include <math.h>

#define Ndim  64
#define Sdim  512
#define Hdim  1024
#define IOdim 64

// ---------------- scratch ----------------
__device__ unsigned g_OShp[(size_t)IOdim * 512];
__device__ unsigned g_OSlp[(size_t)IOdim * 512];
__device__ unsigned g_Wohp[(size_t)1024 * 1024];      // [kp][n]
__device__ unsigned g_Wolp[(size_t)1024 * 1024];
__device__ unsigned g_Wchp[(size_t)32768 * 64];       // [kp][j]
__device__ unsigned g_Wclp[(size_t)32768 * 64];
__device__ float    g_Spart[(size_t)2 * Ndim * IOdim * Sdim];   // score K-partials
__device__ unsigned g_Php [(size_t)Ndim * IOdim * 256];
__device__ unsigned g_Plp [(size_t)Ndim * IOdim * 256];
__device__ unsigned g_mixhp[(size_t)Ndim * IOdim * 512];
__device__ unsigned g_mixlp[(size_t)Ndim * IOdim * 512];
__device__ unsigned g_Thp [(size_t)Ndim * IOdim * 512];
__device__ unsigned g_Tlp [(size_t)Ndim * IOdim * 512];
__device__ float    g_c0p [(size_t)16 * IOdim * Hdim];
__device__ float    g_c0  [(size_t)IOdim * Hdim];
__device__ float    g_part[(size_t)256 * Ndim * IOdim];

// ---------------- helpers ----------------
__device__ __forceinline__ unsigned bfbits(float x) {
    unsigned u = __float_as_uint(x);
    return (u + 0x7fffu + ((u >> 16) & 1u)) & 0xffff0000u;
}
__device__ __forceinline__ void split_pair(float x0, float x1,
                                           unsigned &hw, unsigned &lw) {
    const unsigned h0 = bfbits(x0), h1 = bfbits(x1);
    const unsigned l0 = bfbits(x0 - __uint_as_float(h0));
    const unsigned l1 = bfbits(x1 - __uint_as_float(h1));
    hw = (h0 >> 16) | h1;
    lw = (l0 >> 16) | l1;
}
__device__ __forceinline__ unsigned pack_bf(float x0, float x1) {
    return (bfbits(x0) >> 16) | bfbits(x1);
}
__device__ __forceinline__ float fast_tanh(float x) {
    const float e = __expf(2.0f * x);
    return __fdividef(e - 1.0f, e + 1.0f);
}
__device__ __forceinline__ void mma16(float (&d)[4], const unsigned (&a)[4],
                                      const unsigned (&b)[2]) {
    asm volatile(
        "mma.sync.aligned.m16n8k16.row.col.f32.bf16.bf16.f32 "
        "{%0,%1,%2,%3}, {%4,%5,%6,%7}, {%8,%9}, {%0,%1,%2,%3};"
        : "+f"(d[0]), "+f"(d[1]), "+f"(d[2]), "+f"(d[3])
        : "r"(a[0]), "r"(a[1]), "r"(a[2]), "r"(a[3]), "r"(b[0]), "r"(b[1]));
}
__device__ __forceinline__ void cpa16(unsigned* smem_ptr, const void* gptr) {
    unsigned s = (unsigned)__cvta_generic_to_shared(smem_ptr);
    asm volatile("cp.async.ca.shared.global [%0], [%1], 16;" :: "r"(s), "l"(gptr));
}
#define CP_COMMIT() asm volatile("cp.async.commit_group;")
#define CP_WAIT1()  asm volatile("cp.async.wait_group 1;")
#define CP_WAIT0()  asm volatile("cp.async.wait_group 0;")

constexpr int AST = 12;
constexpr int BKN = 264;
constexpr int BNK = 12;

// ---------------------------------------------------------------------------
// 2-stage 64x256 core (MODE 0: packed B; MODE 1: fp32 [k][n] B; MODE 2: fp32 [n][k] B)
// ---------------------------------------------------------------------------
template<int MODE>
__device__ __forceinline__ void gemm_pipe(
    const unsigned* __restrict__ Ahp, const unsigned* __restrict__ Alp, int lda_w,
    const void* __restrict__ Bp1, const void* __restrict__ Bp2, int ldb,
    int n0, int K,
    unsigned* AshB, unsigned* AslB, unsigned* BshB, unsigned* BslB,
    float (&acc)[4][4][4])
{
    const int tid = threadIdx.x, lane = tid & 31, warp = tid >> 5;
    const int g = lane >> 2, t = lane & 3;
    const int nkt = K >> 4;
    float4 br[4];

    auto stageA = [&](int st, int kt) {
        const int kw0 = kt << 3;
        if (MODE == 2) {
            if (tid < 128) {
                const int row = tid >> 1, wj = (tid & 1) * 4;
                cpa16(AshB + st * 64 * AST + row * AST + wj,
                      Ahp + (size_t)row * lda_w + kw0 + wj);
            }
        } else {
            const int row = (tid & 127) >> 1, wj = (tid & 1) * 4;
            const unsigned* src = (tid < 128 ? Ahp : Alp) + (size_t)row * lda_w + kw0 + wj;
            unsigned* dst = (tid < 128 ? AshB : AslB) + st * 64 * AST + row * AST + wj;
            cpa16(dst, src);
        }
    };
    auto stageB0 = [&](int st, int kt) {
        const int kw0 = kt << 3;
        const unsigned* Bh = (const unsigned*)Bp1;
        const unsigned* Bl = (const unsigned*)Bp2;
#pragma unroll
        for (int j = 0; j < 2; j++) {
            const int ch = tid * 2 + j;
            const int row = ch >> 6, c4 = (ch & 63) * 4;
            cpa16(BshB + st * 8 * BKN + row * BKN + c4,
                  Bh + (size_t)(kw0 + row) * ldb + n0 + c4);
            cpa16(BslB + st * 8 * BKN + row * BKN + c4,
                  Bl + (size_t)(kw0 + row) * ldb + n0 + c4);
        }
    };
    auto ldgB1 = [&](int kt) {
        const float* B = (const float*)Bp1;
        const int k0 = kt << 4;
        const int kp = tid >> 5, c = (tid & 31) * 8;
        const float* r0 = B + (size_t)(k0 + 2 * kp) * ldb + n0 + c;
        br[0] = *reinterpret_cast<const float4*>(r0);
        br[1] = *reinterpret_cast<const float4*>(r0 + 4);
        br[2] = *reinterpret_cast<const float4*>(r0 + ldb);
        br[3] = *reinterpret_cast<const float4*>(r0 + ldb + 4);
    };
    auto stsB1 = [&]() {
        const int kp = tid >> 5, c = (tid & 31) * 8;
        unsigned hw[8], lw[8];
        split_pair(br[0].x, br[2].x, hw[0], lw[0]);
        split_pair(br[0].y, br[2].y, hw[1], lw[1]);
        split_pair(br[0].z, br[2].z, hw[2], lw[2]);
        split_pair(br[0].w, br[2].w, hw[3], lw[3]);
        split_pair(br[1].x, br[3].x, hw[4], lw[4]);
        split_pair(br[1].y, br[3].y, hw[5], lw[5]);
        split_pair(br[1].z, br[3].z, hw[6], lw[6]);
        split_pair(br[1].w, br[3].w, hw[7], lw[7]);
        *reinterpret_cast<uint4*>(BshB + kp * BKN + c)     = make_uint4(hw[0], hw[1], hw[2], hw[3]);
        *reinterpret_cast<uint4*>(BshB + kp * BKN + c + 4) = make_uint4(hw[4], hw[5], hw[6], hw[7]);
        *reinterpret_cast<uint4*>(BslB + kp * BKN + c)     = make_uint4(lw[0], lw[1], lw[2], lw[3]);
        *reinterpret_cast<uint4*>(BslB + kp * BKN + c + 4) = make_uint4(lw[4], lw[5], lw[6], lw[7]);
    };
    auto ldgB2 = [&](int kt) {
        const float* B = (const float*)Bp1;
        const int k0 = kt << 4, kq = tid & 3;
#pragma unroll
        for (int p = 0; p < 4; p++) {
            const int s = (tid >> 2) + 64 * p;
            br[p] = *reinterpret_cast<const float4*>(
                B + (size_t)(n0 + s) * ldb + k0 + kq * 4);
        }
    };
    auto stsB2 = [&]() {
        const int kq = tid & 3;
#pragma unroll
        for (int p = 0; p < 4; p++) {
            const int s = (tid >> 2) + 64 * p;
            *reinterpret_cast<uint2*>(BshB + s * BNK + kq * 2) =
                make_uint2(pack_bf(br[p].x, br[p].y), pack_bf(br[p].z, br[p].w));
        }
    };

    stageA(0, 0);
    if (MODE == 0) stageB0(0, 0);
    CP_COMMIT();
    if (MODE == 1) ldgB1(0);
    if (MODE == 2) ldgB2(0);

    for (int kt = 0; kt < nkt; kt++) {
        const int st = kt & 1;
        __syncthreads();
        if (MODE == 1) stsB1();
        if (MODE == 2) stsB2();
        if (kt + 1 < nkt) {
            stageA(st ^ 1, kt + 1);
            if (MODE == 0) stageB0(st ^ 1, kt + 1);
            CP_COMMIT();
            if (MODE == 1) ldgB1(kt + 1);
            if (MODE == 2) ldgB2(kt + 1);
            CP_WAIT1();
        } else {
            CP_WAIT0();
        }
        __syncthreads();

        const unsigned* Ash = AshB + st * 64 * AST;
        const unsigned* Asl = AslB + st * 64 * AST;
        const unsigned* Bsc = (MODE == 0) ? BshB + st * 8 * BKN : BshB;
        const unsigned* Bsd = (MODE == 0) ? BslB + st * 8 * BKN : BslB;

        unsigned Ahf[4][4];
#pragma unroll
        for (int mi = 0; mi < 4; mi++) {
            const int r = (16 * mi + g) * AST;
            Ahf[mi][0] = Ash[r + t];        Ahf[mi][1] = Ash[r + 8 * AST + t];
            Ahf[mi][2] = Ash[r + t + 4];    Ahf[mi][3] = Ash[r + 8 * AST + t + 4];
        }
        unsigned Bhf[4][2];
#pragma unroll
        for (int ni = 0; ni < 4; ni++) {
            const int col = warp * 32 + ni * 8 + g;
            if (MODE == 2) {
                Bhf[ni][0] = Bsc[col * BNK + t];   Bhf[ni][1] = Bsc[col * BNK + t + 4];
            } else {
                Bhf[ni][0] = Bsc[t * BKN + col];   Bhf[ni][1] = Bsc[(t + 4) * BKN + col];
            }
        }
#pragma unroll
        for (int ni = 0; ni < 4; ni++)
#pragma unroll
            for (int mi = 0; mi < 4; mi++) mma16(acc[mi][ni], Ahf[mi], Bhf[ni]);

        if (MODE != 2) {
            unsigned Alf[4][4], Blf[4][2];
#pragma unroll
            for (int mi = 0; mi < 4; mi++) {
                const int r = (16 * mi + g) * AST;
                Alf[mi][0] = Asl[r + t];        Alf[mi][1] = Asl[r + 8 * AST + t];
                Alf[mi][2] = Asl[r + t + 4];    Alf[mi][3] = Asl[r + 8 * AST + t + 4];
            }
#pragma unroll
            for (int ni = 0; ni < 4; ni++) {
                const int col = warp * 32 + ni * 8 + g;
                Blf[ni][0] = Bsd[t * BKN + col];   Blf[ni][1] = Bsd[(t + 4) * BKN + col];
            }
#pragma unroll
            for (int ni = 0; ni < 4; ni++)
#pragma unroll
                for (int mi = 0; mi < 4; mi++) mma16(acc[mi][ni], Ahf[mi], Blf[ni]);
#pragma unroll
            for (int ni = 0; ni < 4; ni++)
#pragma unroll
                for (int mi = 0; mi < 4; mi++) mma16(acc[mi][ni], Alf[mi], Bhf[ni]);
        }
    }
}

// ---------------- prep kernels ----------------
__global__ __launch_bounds__(256) void k_prep_os(const float* __restrict__ OS) {
    const int gid = blockIdx.x * 256 + threadIdx.x;
    const float2 v = *reinterpret_cast<const float2*>(OS + 2 * (size_t)gid);
    split_pair(v.x, v.y, g_OShp[gid], g_OSlp[gid]);
}
__global__ __launch_bounds__(256) void k_prep_wo(const float* __restrict__ Wo) {
    const int gid = blockIdx.x * 256 + threadIdx.x;
    const int kp = gid >> 10, n = gid & 1023;
    split_pair(Wo[(size_t)(2 * kp) * 1024 + n], Wo[(size_t)(2 * kp + 1) * 1024 + n],
               g_Wohp[gid], g_Wolp[gid]);
}
__global__ __launch_bounds__(256) void k_prep_wc(const float* __restrict__ Wc) {
    const int gid = blockIdx.x * 256 + threadIdx.x;
    const int kp = gid >> 6, j = gid & 63;
    split_pair(Wc[(size_t)(2 * kp) * 64 + j], Wc[(size_t)(2 * kp + 1) * 64 + j],
               g_Wchp[gid], g_Wclp[gid]);
}

// ---------------- c0 ----------------
__global__ __launch_bounds__(256, 2)
void k_c0(void)
{
    __shared__ unsigned Ash[2 * 64 * AST], Asl[2 * 64 * AST];
    __shared__ unsigned Bsh[2 * 8 * BKN],  Bsl[2 * 8 * BKN];
    const int n0 = blockIdx.x * 256, ks = blockIdx.y;
    float acc[4][4][4] = {};
    gemm_pipe<0>(g_OShp + ks * 32, g_OSlp + ks * 32, 512,
                 g_Wohp + (size_t)(512 + ks * 32) * 1024,
                 g_Wolp + (size_t)(512 + ks * 32) * 1024, 1024,
                 n0, 64, Ash, Asl, Bsh, Bsl, acc);
    const int lane = threadIdx.x & 31, warp = threadIdx.x >> 5;
    const int g = lane >> 2, t = lane & 3;
    float* Cp = g_c0p + (size_t)ks * IOdim * Hdim;
#pragma unroll
    for (int mi = 0; mi < 4; mi++)
#pragma unroll
        for (int ni = 0; ni < 4; ni++) {
            const int r0 = 16 * mi + g, c = n0 + warp * 32 + ni * 8 + 2 * t;
            *reinterpret_cast<float2*>(Cp + (size_t)r0 * Hdim + c) =
                make_float2(acc[mi][ni][0], acc[mi][ni][1]);
            *reinterpret_cast<float2*>(Cp + (size_t)(r0 + 8) * Hdim + c) =
                make_float2(acc[mi][ni][2], acc[mi][ni][3]);
        }
}
__global__ __launch_bounds__(256) void k_c0red(const float* __restrict__ bo) {
    const int gid = blockIdx.x * 256 + threadIdx.x;
    float acc = bo[gid & (Hdim - 1)];
#pragma unroll
    for (int p = 0; p < 16; p++) acc += g_c0p[(size_t)p * IOdim * Hdim + gid];
    g_c0[gid] = acc;
}

// ---------------- scores (K-split 2, 1-term bf16) ----------------
__global__ __launch_bounds__(256, 2)
void k_scores(const float* __restrict__ states)
{
    __shared__ unsigned Ash[2 * 64 * AST];
    __shared__ unsigned Bsh[256 * BNK];
    const int n = blockIdx.z, ks = blockIdx.y, n0 = blockIdx.x * 256;
    float acc[4][4][4] = {};
    gemm_pipe<2>(g_OShp + ks * 256, nullptr, 512,
                 states + (size_t)n * Sdim * Hdim + ks * 512, nullptr, Hdim,
                 n0, 512, Ash, Ash, Bsh, Bsh, acc);
    const int lane = threadIdx.x & 31, warp = threadIdx.x >> 5;
    const int g = lane >> 2, t = lane & 3;
    float* Cn = g_Spart + ((size_t)ks * Ndim + n) * IOdim * Sdim;
#pragma unroll
    for (int mi = 0; mi < 4; mi++)
#pragma unroll
        for (int ni = 0; ni < 4; ni++) {
            const int r0 = 16 * mi + g, c = n0 + warp * 32 + ni * 8 + 2 * t;
            *reinterpret_cast<float2*>(Cn + (size_t)r0 * Sdim + c) =
                make_float2(acc[mi][ni][0], acc[mi][ni][1]);
            *reinterpret_cast<float2*>(Cn + (size_t)(r0 + 8) * Sdim + c) =
                make_float2(acc[mi][ni][2], acc[mi][ni][3]);
        }
}

// ---------------- softmax (sums K-partials) ----------------
__global__ __launch_bounds__(256)
void k_softmax(void)
{
    const int warp = threadIdx.x >> 5, lane = threadIdx.x & 31;
    const size_t row = (size_t)blockIdx.x * 8 + warp;
    const float* s0 = g_Spart + row * Sdim + lane * 16;
    const float* s1 = s0 + (size_t)Ndim * IOdim * Sdim;
    float v[16];
#pragma unroll
    for (int j = 0; j < 4; j++) {
        const float4 a = *reinterpret_cast<const float4*>(s0 + 4 * j);
        const float4 b = *reinterpret_cast<const float4*>(s1 + 4 * j);
        v[4*j] = a.x + b.x; v[4*j+1] = a.y + b.y;
        v[4*j+2] = a.z + b.z; v[4*j+3] = a.w + b.w;
    }
    float mx = v[0];
#pragma unroll
    for (int q = 1; q < 16; q++) mx = fmaxf(mx, v[q]);
#pragma unroll
    for (int off = 16; off > 0; off >>= 1)
        mx = fmaxf(mx, __shfl_xor_sync(0xffffffffu, mx, off));
    float sum = 0.f;
#pragma unroll
    for (int q = 0; q < 16; q++) { v[q] = __expf(v[q] - mx); sum += v[q]; }
#pragma unroll
    for (int off = 16; off > 0; off >>= 1)
        sum += __shfl_xor_sync(0xffffffffu, sum, off);
    const float inv = 1.0f / sum;
    unsigned hw[8], lw[8];
#pragma unroll
    for (int j = 0; j < 8; j++) split_pair(v[2*j] * inv, v[2*j+1] * inv, hw[j], lw[j]);
    unsigned* ph = g_Php + row * 256 + lane * 8;
    unsigned* pl = g_Plp + row * 256 + lane * 8;
    *reinterpret_cast<uint4*>(ph)     = make_uint4(hw[0], hw[1], hw[2], hw[3]);
    *reinterpret_cast<uint4*>(ph + 4) = make_uint4(hw[4], hw[5], hw[6], hw[7]);
    *reinterpret_cast<uint4*>(pl)     = make_uint4(lw[0], lw[1], lw[2], lw[3]);
    *reinterpret_cast<uint4*>(pl + 4) = make_uint4(lw[4], lw[5], lw[6], lw[7]);
}

// ---------------- mix ----------------
__global__ __launch_bounds__(256, 2)
void k_mix(const float* __restrict__ states)
{
    __shared__ unsigned Ash[2 * 64 * AST], Asl[2 * 64 * AST];
    __shared__ unsigned Bsh[8 * BKN],      Bsl[8 * BKN];
    const int n = blockIdx.y, n0 = blockIdx.x * 256;
    float acc[4][4][4] = {};
    gemm_pipe<1>(g_Php + (size_t)n * IOdim * 256, g_Plp + (size_t)n * IOdim * 256, 256,
                 states + (size_t)n * Sdim * Hdim, nullptr, Hdim,
                 n0, Sdim, Ash, Asl, Bsh, Bsl, acc);
    const int lane = threadIdx.x & 31, warp = threadIdx.x >> 5;
    const int g = lane >> 2, t = lane & 3;
    unsigned* Mh = g_mixhp + (size_t)n * IOdim * 512;
    unsigned* Ml = g_mixlp + (size_t)n * IOdim * 512;
#pragma unroll
    for (int mi = 0; mi < 4; mi++)
#pragma unroll
        for (int ni = 0; ni < 4; ni++) {
            const int r0 = 16 * mi + g;
            const int wc = ((n0 + warp * 32 + ni * 8) >> 1) + t;
            unsigned h, l;
            split_pair(acc[mi][ni][0], acc[mi][ni][1], h, l);
            Mh[(size_t)r0 * 512 + wc] = h;  Ml[(size_t)r0 * 512 + wc] = l;
            split_pair(acc[mi][ni][2], acc[mi][ni][3], h, l);
            Mh[(size_t)(r0 + 8) * 512 + wc] = h;  Ml[(size_t)(r0 + 8) * 512 + wc] = l;
        }
}

// ---------------- outlin: 2 states per block, M=128, 512 thr, 3-stage ------
constexpr int OUT_SMEM_W = 3 * 128 * AST * 2 + 3 * 8 * BKN * 2;   // words

__global__ __launch_bounds__(512, 1)
void k_outlin(void)
{
    extern __shared__ unsigned smem[];
    unsigned* Ash = smem;
    unsigned* Asl = Ash + 3 * 128 * AST;
    unsigned* Bsh = Asl + 3 * 128 * AST;
    unsigned* Bsl = Bsh + 3 * 8 * BKN;

    const int tid = threadIdx.x, lane = tid & 31, warp = tid >> 5;
    const int g = lane >> 2, t = lane & 3;
    const int mg = warp >> 3, wn = warp & 7;
    const int npair = blockIdx.y, n0 = blockIdx.x * 256;
    const unsigned* Ahp = g_mixhp + (size_t)npair * 65536;   // 128 rows x 512 words
    const unsigned* Alp = g_mixlp + (size_t)npair * 65536;

    float acc[4][4][4] = {};

    auto stage = [&](int buf, int kt) {
        const int kw0 = kt << 3;
        {   // A: 2048 words, 512 cpa16
            const int arr = tid >> 8, row = (tid & 255) >> 1, wj = (tid & 1) * 4;
            const unsigned* src = (arr ? Alp : Ahp) + (size_t)row * 512 + kw0 + wj;
            unsigned* dst = (arr ? Asl : Ash) + buf * 128 * AST + row * AST + wj;
            cpa16(dst, src);
        }
#pragma unroll
        for (int j = 0; j < 2; j++) {   // B: 4096 words, 1024 cpa16
            const int ch = tid * 2 + j;
            const int arr = ch >> 9, rc = ch & 511;
            const int row = rc >> 6, c4 = (rc & 63) * 4;
            const unsigned* src = (arr ? g_Wolp : g_Wohp) + (size_t)(kw0 + row) * 1024 + n0 + c4;
            unsigned* dst = (arr ? Bsl : Bsh) + buf * 8 * BKN + row * BKN + c4;
            cpa16(dst, src);
        }
    };

    const int nkt = 64;
    stage(0, 0); CP_COMMIT();
    stage(1, 1); CP_COMMIT();

    for (int kt = 0; kt < nkt; kt++) {
        const int buf = kt % 3;
        if (kt + 1 < nkt) CP_WAIT1(); else CP_WAIT0();
        __syncthreads();
        if (kt + 2 < nkt) { stage((kt + 2) % 3, kt + 2); CP_COMMIT(); }

        const unsigned* As = Ash + buf * 128 * AST;
        const unsigned* Al = Asl + buf * 128 * AST;
        const unsigned* Bs = Bsh + buf * 8 * BKN;
        const unsigned* Bl = Bsl + buf * 8 * BKN;

        unsigned Ahf[4][4], Alf[4][4];
#pragma unroll
        for (int mi = 0; mi < 4; mi++) {
            const int r = (mg * 64 + 16 * mi + g) * AST;
            Ahf[mi][0] = As[r + t];        Ahf[mi][1] = As[r + 8 * AST + t];
            Ahf[mi][2] = As[r + t + 4];    Ahf[mi][3] = As[r + 8 * AST + t + 4];
            Alf[mi][0] = Al[r + t];        Alf[mi][1] = Al[r + 8 * AST + t];
            Alf[mi][2] = Al[r + t + 4];    Alf[mi][3] = Al[r + 8 * AST + t + 4];
        }
        unsigned Bhf[4][2], Blf[4][2];
#pragma unroll
        for (int ni = 0; ni < 4; ni++) {
            const int col = wn * 32 + ni * 8 + g;
            Bhf[ni][0] = Bs[t * BKN + col];   Bhf[ni][1] = Bs[(t + 4) * BKN + col];
            Blf[ni][0] = Bl[t * BKN + col];   Blf[ni][1] = Bl[(t + 4) * BKN + col];
        }
#pragma unroll
        for (int ni = 0; ni < 4; ni++)
#pragma unroll
            for (int mi = 0; mi < 4; mi++) mma16(acc[mi][ni], Ahf[mi], Bhf[ni]);
#pragma unroll
        for (int ni = 0; ni < 4; ni++)
#pragma unroll
            for (int mi = 0; mi < 4; mi++) mma16(acc[mi][ni], Ahf[mi], Blf[ni]);
#pragma unroll
        for (int ni = 0; ni < 4; ni++)
#pragma unroll
            for (int mi = 0; mi < 4; mi++) mma16(acc[mi][ni], Alf[mi], Bhf[ni]);
    }

    const int n = npair * 2 + mg;
    unsigned* Th = g_Thp + (size_t)n * IOdim * 512;
    unsigned* Tl = g_Tlp + (size_t)n * IOdim * 512;
#pragma unroll
    for (int mi = 0; mi < 4; mi++)
#pragma unroll
        for (int ni = 0; ni < 4; ni++) {
            const int i = 16 * mi + g, c = n0 + wn * 32 + ni * 8 + 2 * t;
            const int wc = c >> 1;
            const float2 b0 = *reinterpret_cast<const float2*>(g_c0 + (size_t)i * Hdim + c);
            const float2 b1 = *reinterpret_cast<const float2*>(g_c0 + (size_t)(i + 8) * Hdim + c);
            unsigned h, l;
            split_pair(fast_tanh(acc[mi][ni][0] + b0.x),
                       fast_tanh(acc[mi][ni][1] + b0.y), h, l);
            Th[(size_t)i * 512 + wc] = h;  Tl[(size_t)i * 512 + wc] = l;
            split_pair(fast_tanh(acc[mi][ni][2] + b1.x),
                       fast_tanh(acc[mi][ni][3] + b1.y), h, l);
            Th[(size_t)(i + 8) * 512 + wc] = h;  Tl[(size_t)(i + 8) * 512 + wc] = l;
        }
}

// ---------------- logits: 256 K-chunks, 3-stage ----------------
constexpr int BKL = 72;
__global__ __launch_bounds__(256, 2)
void k_logits(void)
{
    __shared__ unsigned Ash[3 * 64 * AST], Asl[3 * 64 * AST];
    __shared__ unsigned Bsh[3 * 8 * BKL],  Bsl[3 * 8 * BKL];
    const int chunk = blockIdx.x;                 // 256 chunks of K=256
    const unsigned* Ahp = g_Thp + (size_t)chunk * 128;
    const unsigned* Alp = g_Tlp + (size_t)chunk * 128;
    const unsigned* Bhp = g_Wchp + (size_t)chunk * 128 * 64;
    const unsigned* Blp = g_Wclp + (size_t)chunk * 128 * 64;

    const int tid = threadIdx.x, lane = tid & 31, warp = tid >> 5;
    const int g = lane >> 2, t = lane & 3;
    float acc[4][4] = {};

    auto stage = [&](int buf, int kt) {
        const int kw0 = kt << 3;
        {
            const int row = (tid & 127) >> 1, wj = (tid & 1) * 4;
            const unsigned* src = (tid < 128 ? Ahp : Alp) + (size_t)row * 32768 + kw0 + wj;
            unsigned* dst = (tid < 128 ? Ash : Asl) + buf * 64 * AST + row * AST + wj;
            cpa16(dst, src);
        }
        {
            const int ch = tid & 127;
            const int row = ch >> 4, c4 = (ch & 15) * 4;
            const unsigned* src = (tid < 128 ? Bhp : Blp) + (size_t)(kw0 + row) * 64 + c4;
            unsigned* dst = (tid < 128 ? Bsh : Bsl) + buf * 8 * BKL + row * BKL + c4;
            cpa16(dst, src);
        }
    };

    const int nkt = 16;
    stage(0, 0); CP_COMMIT();
    stage(1, 1); CP_COMMIT();
    for (int kt = 0; kt < nkt; kt++) {
        const int buf = kt % 3;
        if (kt + 1 < nkt) CP_WAIT1(); else CP_WAIT0();
        __syncthreads();
        if (kt + 2 < nkt) { stage((kt + 2) % 3, kt + 2); CP_COMMIT(); }

        const unsigned* As = Ash + buf * 64 * AST;
        const unsigned* Al = Asl + buf * 64 * AST;
        const unsigned* Bs = Bsh + buf * 8 * BKL;
        const unsigned* Bl = Bsl + buf * 8 * BKL;

        unsigned Ahf[4][4], Alf[4][4];
#pragma unroll
        for (int mi = 0; mi < 4; mi++) {
            const int r = (16 * mi + g) * AST;
            Ahf[mi][0] = As[r + t];        Ahf[mi][1] = As[r + 8 * AST + t];
            Ahf[mi][2] = As[r + t + 4];    Ahf[mi][3] = As[r + 8 * AST + t + 4];
            Alf[mi][0] = Al[r + t];        Alf[mi][1] = Al[r + 8 * AST + t];
            Alf[mi][2] = Al[r + t + 4];    Alf[mi][3] = Al[r + 8 * AST + t + 4];
        }
        const int col = warp * 8 + g;
        unsigned bh[2] = { Bs[t * BKL + col], Bs[(t + 4) * BKL + col] };
        unsigned bl[2] = { Bl[t * BKL + col], Bl[(t + 4) * BKL + col] };
#pragma unroll
        for (int mi = 0; mi < 4; mi++) mma16(acc[mi], Ahf[mi], bh);
#pragma unroll
        for (int mi = 0; mi < 4; mi++) mma16(acc[mi], Ahf[mi], bl);
#pragma unroll
        for (int mi = 0; mi < 4; mi++) mma16(acc[mi], Alf[mi], bh);
    }
    float* Cp = g_part + (size_t)chunk * Ndim * IOdim;
#pragma unroll
    for (int mi = 0; mi < 4; mi++) {
        const int r0 = 16 * mi + g, c = warp * 8 + 2 * t;
        *reinterpret_cast<float2*>(Cp + (size_t)r0 * IOdim + c) =
            make_float2(acc[mi][0], acc[mi][1]);
        *reinterpret_cast<float2*>(Cp + (size_t)(r0 + 8) * IOdim + c) =
            make_float2(acc[mi][2], acc[mi][3]);
    }
}

__global__ __launch_bounds__(256)
void k_reduce(const float* __restrict__ bc, float* __restrict__ out)
{
    const int gid = blockIdx.x * 256 + threadIdx.x;
    float acc = bc[gid & 63];
#pragma unroll 8
    for (int ch = 0; ch < 256; ch++) acc += g_part[(size_t)ch * 4096 + gid];
    out[gid] = acc;
}

// ===========================================================================
extern "C" void kernel_launch(void* const* d_in, const int* in_sizes, int n_in,
                              void* d_out, int out_size)
{
    const float* states = (const float*)d_in[0];
    const float* OS     = (const float*)d_in[1];
    const float* Wo     = (const float*)d_in[2];
    const float* bo     = (const float*)d_in[3];
    const float* Wc     = (const float*)d_in[4];
    const float* bc     = (const float*)d_in[5];
    float* out = (float*)d_out;

    static bool attr_done = false;
    if (!attr_done) {
        cudaFuncSetAttribute(k_outlin, cudaFuncAttributeMaxDynamicSharedMemorySize,
                             OUT_SMEM_W * (int)sizeof(unsigned));
        attr_done = true;
    }

    k_prep_os<<<128,  256>>>(OS);
    k_prep_wo<<<4096, 256>>>(Wo);
    k_prep_wc<<<8192, 256>>>(Wc);
    k_c0     <<<dim3(4, 16), 256>>>();
    k_c0red  <<<256,  256>>>(bo);
    k_scores <<<dim3(2, 2, 64), 256>>>(states);
    k_softmax<<<512,  256>>>();
    k_mix    <<<dim3(4, 64), 256>>>(states);
    k_outlin <<<dim3(4, 32), 512, OUT_SMEM_W * sizeof(unsigned)>>>();
    k_logits <<<256,  256>>>();
    k_reduce <<<16,   256>>>(bc, out);
}